// round 12
// baseline (speedup 1.0000x reference)
#include <cuda_runtime.h>
#include <cuda_bf16.h>
#include <stdint.h>

#define N_NODES 131072
#define N_EDGES 256
#define IN_C    128
#define OUT_C   256
#define M_TILE  128
#define N_TILES (N_NODES / M_TILE)   // 1024
#define SAT_NODES 8192

// ---------------- device scratch (no allocations allowed) ----------------
__device__ __align__(16) uint32_t g_nodeMask[N_NODES * 8];   // 4 MB (fallback only)
__device__ uint32_t g_edgeMask[N_EDGES * 8];                 // 8 KB
__device__ float    g_scale[N_NODES];
__device__ int      g_sat;

// ---------------- K0: zero edge-mask table + flag ----------------
__global__ void k_zero() {
    int i = blockIdx.x * blockDim.x + threadIdx.x;
    if (i < N_EDGES * 8) g_edgeMask[i] = 0u;
    if (i == 0) g_sat = 0;
}

// ---------------- K1: pack sample nodes -> edge masks + per-node deg ----------------
__global__ void __launch_bounds__(512) k_pack1(const float* __restrict__ H) {
    __shared__ uint32_t sEdge[N_EDGES * 8];
    const int tid  = threadIdx.x;
    const int lane = tid & 31;
    const int w    = tid & 7;

    for (int i = tid; i < N_EDGES * 8; i += 512) sEdge[i] = 0u;
    __syncthreads();

    const int node = blockIdx.x * 64 + (tid >> 3);   // 128 blocks x 64 nodes
    {
        const float4* hp = reinterpret_cast<const float4*>(
            H + (size_t)node * N_EDGES + w * 32);
        uint32_t word = 0;
        #pragma unroll
        for (int j = 0; j < 8; j++) {
            float4 f = hp[j];
            word |= (f.x >= 0.5f ? 1u : 0u) << (j * 4 + 0);
            word |= (f.y >= 0.5f ? 1u : 0u) << (j * 4 + 1);
            word |= (f.z >= 0.5f ? 1u : 0u) << (j * 4 + 2);
            word |= (f.w >= 0.5f ? 1u : 0u) << (j * 4 + 3);
        }
        g_nodeMask[node * 8 + w] = word;
        int d = __popc(word);
        d += __shfl_xor_sync(0xffffffffu, d, 1);
        d += __shfl_xor_sync(0xffffffffu, d, 2);
        d += __shfl_xor_sync(0xffffffffu, d, 4);
        if (w == 0) g_scale[node] = (float)d;     // raw deg; k_sat converts

        uint32_t wd[8];
        #pragma unroll
        for (int j = 0; j < 8; j++)
            wd[j] = __shfl_sync(0xffffffffu, word, (lane & ~7) | j);
        uint32_t m = word;
        while (m) {
            int b = __ffs(m) - 1;
            m &= m - 1;
            int e = w * 32 + b;
            #pragma unroll
            for (int j = 0; j < 8; j++) {
                uint32_t cur = sEdge[e * 8 + j];
                if ((cur & wd[j]) != wd[j]) atomicOr(&sEdge[e * 8 + j], wd[j]);
            }
        }
    }
    __syncthreads();
    for (int i = tid; i < N_EDGES * 8; i += 512) {
        uint32_t v = sEdge[i];
        if (v) atomicOr(&g_edgeMask[i], v);
    }
}

// ---------------- K2: saturation check + scale for sample nodes ----------------
__global__ void __launch_bounds__(256) k_sat() {
    __shared__ int nf;
    const int tid = threadIdx.x;
    if (tid == 0) nf = 0;
    __syncthreads();
    int bad = 0;
    for (int i = tid; i < N_EDGES * 8; i += 256)
        bad += (g_edgeMask[i] != 0xffffffffu);
    atomicAdd(&nf, bad);
    __syncthreads();
    const bool sat = (nf == 0);
    if (blockIdx.x == 0 && tid == 0) g_sat = sat ? 1 : 0;
    if (sat) {
        const int node = blockIdx.x * 256 + tid;     // 32 x 256 = 8192
        if (node < SAT_NODES) {
            float d = g_scale[node];
            g_scale[node] = (d > 0.0f) ? (1.0f + rsqrtf(d + 256.0f)) : 1.0f;
        }
    }
}

// ---------------- K3: stream remaining nodes (coalesced saturated path) ----------------
__global__ void __launch_bounds__(512) k_pack2(const float* __restrict__ H) {
    __shared__ uint32_t sEdge[N_EDGES * 8];
    const int tid  = threadIdx.x;
    const int lane = tid & 31;
    const bool sat = (g_sat != 0);

    if (sat) {
        const int wId  = tid >> 5;          // 16 warps
        const int l16  = lane & 15;
        const int half = lane >> 4;
        for (int base = SAT_NODES + blockIdx.x * 32; base < N_NODES;
             base += gridDim.x * 32) {
            const int node = base + wId * 2 + half;
            int cnt = 0;
            if (node < N_NODES) {
                const float4* hp = reinterpret_cast<const float4*>(
                    H + (size_t)node * N_EDGES) + l16;
                const float4 v0 = hp[0];
                const float4 v1 = hp[16];
                const float4 v2 = hp[32];
                const float4 v3 = hp[48];
                cnt  = (v0.x >= 0.5f) + (v0.y >= 0.5f) + (v0.z >= 0.5f) + (v0.w >= 0.5f);
                cnt += (v1.x >= 0.5f) + (v1.y >= 0.5f) + (v1.z >= 0.5f) + (v1.w >= 0.5f);
                cnt += (v2.x >= 0.5f) + (v2.y >= 0.5f) + (v2.z >= 0.5f) + (v2.w >= 0.5f);
                cnt += (v3.x >= 0.5f) + (v3.y >= 0.5f) + (v3.z >= 0.5f) + (v3.w >= 0.5f);
            }
            cnt += __shfl_xor_sync(0xffffffffu, cnt, 1);
            cnt += __shfl_xor_sync(0xffffffffu, cnt, 2);
            cnt += __shfl_xor_sync(0xffffffffu, cnt, 4);
            cnt += __shfl_xor_sync(0xffffffffu, cnt, 8);
            if (l16 == 0 && node < N_NODES)
                g_scale[node] = (cnt > 0) ? (1.0f + rsqrtf((float)(cnt + 256))) : 1.0f;
        }
        return;
    }

    // ---- exact fallback (rare) ----
    const int w = tid & 7;
    for (int i = tid; i < N_EDGES * 8; i += 512) sEdge[i] = 0u;
    __syncthreads();

    for (int base = SAT_NODES + blockIdx.x * 64; base < N_NODES; base += gridDim.x * 64) {
        const int node = base + (tid >> 3);
        const float4* hp = reinterpret_cast<const float4*>(
            H + (size_t)node * N_EDGES + w * 32);
        uint32_t word = 0;
        #pragma unroll
        for (int j = 0; j < 8; j++) {
            float4 f = hp[j];
            word |= (f.x >= 0.5f ? 1u : 0u) << (j * 4 + 0);
            word |= (f.y >= 0.5f ? 1u : 0u) << (j * 4 + 1);
            word |= (f.z >= 0.5f ? 1u : 0u) << (j * 4 + 2);
            word |= (f.w >= 0.5f ? 1u : 0u) << (j * 4 + 3);
        }
        g_nodeMask[node * 8 + w] = word;
        uint32_t wd[8];
        #pragma unroll
        for (int j = 0; j < 8; j++)
            wd[j] = __shfl_sync(0xffffffffu, word, (lane & ~7) | j);
        uint32_t m = word;
        while (m) {
            int b = __ffs(m) - 1;
            m &= m - 1;
            int e = w * 32 + b;
            #pragma unroll
            for (int j = 0; j < 8; j++) {
                uint32_t cur = sEdge[e * 8 + j];
                if ((cur & wd[j]) != wd[j]) atomicOr(&sEdge[e * 8 + j], wd[j]);
            }
        }
    }
    __syncthreads();
    for (int i = tid; i < N_EDGES * 8; i += 512) {
        uint32_t v = sEdge[i];
        if (v) atomicOr(&g_edgeMask[i], v);
    }
}

// ---------------- K4 (fallback, rare): exact scale for ALL nodes ----------------
__global__ void __launch_bounds__(256) k_fb_scale() {
    if (g_sat) return;
    __shared__ uint32_t tbl[N_EDGES * 8];
    const int tid = threadIdx.x;
    for (int i = tid; i < N_EDGES * 8; i += 256) tbl[i] = g_edgeMask[i];
    __syncthreads();

    for (int node = blockIdx.x * 256 + tid; node < N_NODES; node += gridDim.x * 256) {
        const uint4 a = reinterpret_cast<const uint4*>(g_nodeMask)[node * 2 + 0];
        const uint4 b = reinterpret_cast<const uint4*>(g_nodeMask)[node * 2 + 1];
        uint32_t wd[8] = {a.x, a.y, a.z, a.w, b.x, b.y, b.z, b.w};
        int deg = 0;
        #pragma unroll
        for (int j = 0; j < 8; j++) deg += __popc(wd[j]);
        uint32_t acc[8] = {0, 0, 0, 0, 0, 0, 0, 0};
        if (deg) {
            bool fl = false;
            for (int w0 = 0; w0 < 8 && !fl; w0++) {
                uint32_t m = wd[w0];
                while (m) {
                    int bi = __ffs(m) - 1;
                    m &= m - 1;
                    int e = w0 * 32 + bi;
                    uint32_t allones = 0xffffffffu;
                    #pragma unroll
                    for (int j = 0; j < 8; j++) {
                        acc[j] |= tbl[e * 8 + j];
                        allones &= acc[j];
                    }
                    if (allones == 0xffffffffu) { fl = true; break; }
                }
            }
        }
        int dv2 = 0;
        #pragma unroll
        for (int j = 0; j < 8; j++) dv2 += __popc(acc[j]);
        const int dv = deg + dv2;
        float s = 1.0f;
        if (dv > 0) s += rsqrtf((float)dv);
        g_scale[node] = s;
    }
}

// ---------------- K5: GEMM out = scale * (U @ W) + bias ----------------
// 256 threads, M_TILE=128, warp grid 2M x 4N, warp tile 64x64 (acc=128 regs).
// Full 256 cols per pass (no h-loop). ldsm traffic halved vs 32x32 tiles:
// 4 MMAs per ldsm. bf16 AhxBh + fp8 e4m3 corrections (same numerics).
#define SM_BIAS  0                       // 256 floats = 1 KB
#define SM_SCALE 1024                    // 128 floats
#define SM_AH    2048                    // 128 x 256B bf16        32 KB
#define SM_A8    (SM_AH + 32768)         // 128 x 128B fp8         16 KB
#define SM_AL8   (SM_A8 + 16384)         // 128 x 128B fp8         16 KB
#define SM_BH    (SM_AL8 + 16384)        // 256 x 256B bf16        64 KB
#define SM_B8    (SM_BH + 65536)         // 256 x 128B fp8         32 KB
#define SM_BL8   (SM_B8 + 32768)         // 256 x 128B fp8         32 KB
#define SM_TOTAL (SM_BL8 + 32768)        // 198656 bytes

__device__ __forceinline__ uint32_t sw_off(int row, int k) {     // bf16, 256B rows
    return (uint32_t)(row * 256 + ((((k >> 3) ^ (row & 7)) << 4) | ((k & 7) * 2)));
}
__device__ __forceinline__ uint32_t sw8_off(int row, int k) {    // fp8, 128B rows
    return (uint32_t)(row * 128 + ((((k >> 4) ^ (row & 7)) << 4) | (k & 15)));
}

__device__ __forceinline__ uint32_t smem_u32(const void* p) {
    uint32_t a;
    asm("{ .reg .u64 t; cvta.to.shared.u64 t, %1; cvt.u32.u64 %0, t; }"
        : "=r"(a) : "l"(p));
    return a;
}

__device__ __forceinline__ void ldsm_x4(uint32_t* r, uint32_t addr) {
    asm volatile("ldmatrix.sync.aligned.m8n8.x4.shared.b16 {%0,%1,%2,%3}, [%4];"
                 : "=r"(r[0]), "=r"(r[1]), "=r"(r[2]), "=r"(r[3]) : "r"(addr));
}

__device__ __forceinline__ void mma16816(float* c, const uint32_t* a, const uint32_t* b) {
    asm volatile(
        "mma.sync.aligned.m16n8k16.row.col.f32.bf16.bf16.f32 "
        "{%0,%1,%2,%3}, {%4,%5,%6,%7}, {%8,%9}, {%0,%1,%2,%3};"
        : "+f"(c[0]), "+f"(c[1]), "+f"(c[2]), "+f"(c[3])
        : "r"(a[0]), "r"(a[1]), "r"(a[2]), "r"(a[3]), "r"(b[0]), "r"(b[1]));
}

__device__ __forceinline__ void mma_fp8(float* c, const uint32_t* a, const uint32_t* b) {
    asm volatile(
        "mma.sync.aligned.m16n8k32.row.col.f32.e4m3.e4m3.f32 "
        "{%0,%1,%2,%3}, {%4,%5,%6,%7}, {%8,%9}, {%0,%1,%2,%3};"
        : "+f"(c[0]), "+f"(c[1]), "+f"(c[2]), "+f"(c[3])
        : "r"(a[0]), "r"(a[1]), "r"(a[2]), "r"(a[3]), "r"(b[0]), "r"(b[1]));
}

__device__ __forceinline__ uint32_t pack4_e4m3(float f0, float f1, float f2, float f3) {
    uint16_t lo, hi;
    asm("cvt.rn.satfinite.e4m3x2.f32 %0, %1, %2;" : "=h"(lo) : "f"(f1), "f"(f0));
    asm("cvt.rn.satfinite.e4m3x2.f32 %0, %1, %2;" : "=h"(hi) : "f"(f3), "f"(f2));
    return (uint32_t)lo | ((uint32_t)hi << 16);
}

__device__ __forceinline__ void convert8(const float* v, char* smem, int row, int k0,
                                         uint32_t baseH, uint32_t base8, uint32_t baseL8) {
    uint32_t hi[4];
    float r[8];
    #pragma unroll
    for (int i = 0; i < 4; i++) {
        __nv_bfloat16 h0 = __float2bfloat16(v[2 * i + 0]);
        __nv_bfloat16 h1 = __float2bfloat16(v[2 * i + 1]);
        r[2 * i + 0] = (v[2 * i + 0] - __bfloat162float(h0)) * 256.0f;
        r[2 * i + 1] = (v[2 * i + 1] - __bfloat162float(h1)) * 256.0f;
        __nv_bfloat162 hp = __halves2bfloat162(h0, h1);
        hi[i] = *reinterpret_cast<uint32_t*>(&hp);
    }
    *reinterpret_cast<uint4*>(smem + baseH + sw_off(row, k0)) =
        make_uint4(hi[0], hi[1], hi[2], hi[3]);
    const uint32_t o8 = sw8_off(row, k0);
    *reinterpret_cast<uint2*>(smem + base8 + o8) =
        make_uint2(pack4_e4m3(v[0], v[1], v[2], v[3]),
                   pack4_e4m3(v[4], v[5], v[6], v[7]));
    *reinterpret_cast<uint2*>(smem + baseL8 + o8) =
        make_uint2(pack4_e4m3(r[0], r[1], r[2], r[3]),
                   pack4_e4m3(r[4], r[5], r[6], r[7]));
}

__global__ void __launch_bounds__(256, 1)
k_gemm(const float* __restrict__ U, const float* __restrict__ W,
       const float* __restrict__ bias, float* __restrict__ out)
{
    extern __shared__ char smem[];
    const uint32_t sb = smem_u32(smem);
    const int tid  = threadIdx.x;
    const int wid  = tid >> 5;          // 0..7
    const int lane = tid & 31;
    const int wm   = wid >> 2;          // 0..1 (64 rows each)
    const int wn   = wid & 3;           // 0..3 (64 cols each)

    float* sbias  = reinterpret_cast<float*>(smem + SM_BIAS);
    float* sscale = reinterpret_cast<float*>(smem + SM_SCALE);
    if (tid < OUT_C) sbias[tid] = bias[tid];

    // ---- convert W once: B[n][k] = W[k][n] -> BH + B8 + BL8 ----
    #pragma unroll 1
    for (int it = 0; it < 16; it++) {
        const int n  = tid;
        const int k0 = it * 8;
        float v[8];
        #pragma unroll
        for (int i = 0; i < 8; i++) v[i] = W[(size_t)(k0 + i) * OUT_C + n];
        convert8(v, smem, n, k0, SM_BH, SM_B8, SM_BL8);
    }

    const uint32_t xr = lane & 7;
    const int rowBase = wm * 64;
    const uint32_t aRowB = (uint32_t)((rowBase + (lane & 15)) * 256);
    const uint32_t aRow8 = (uint32_t)((rowBase + (lane & 15)) * 128);
    const int nInPair = (lane & 7) + ((lane >> 4) << 3);
    const uint32_t bKcOff = (lane >> 3) & 1;
    const uint32_t aKcOff = lane >> 4;
    const int ncolw = wn * 64;

    for (int tile = blockIdx.x; tile < N_TILES; tile += gridDim.x) {
        const int R0 = tile * M_TILE;

        if (tid < M_TILE) sscale[tid] = g_scale[R0 + tid];
        // load + convert A tile (transient registers; 8 chunks of 8 floats)
        #pragma unroll
        for (int it = 0; it < 8; it++) {
            const int c  = it * 256 + tid;
            const int m  = c >> 4;
            const int k0 = (c & 15) * 8;
            const float4* up = reinterpret_cast<const float4*>(
                U + (size_t)(R0 + m) * IN_C + k0);
            const float4 f0 = up[0];
            const float4 f1 = up[1];
            float v[8] = {f0.x, f0.y, f0.z, f0.w, f1.x, f1.y, f1.z, f1.w};
            convert8(v, smem, m, k0, SM_AH, SM_A8, SM_AL8);
        }
        __syncthreads();

        float acc[128];
        #pragma unroll
        for (int i = 0; i < 128; i++) acc[i] = 0.0f;

        // ---- fp8 correction passes (warp tile 64x64) ----
        #pragma unroll
        for (int kc = 0; kc < 4; kc++) {
            const uint32_t kxA = ((((uint32_t)kc << 1) + aKcOff) ^ xr) << 4;
            uint32_t bofs[4];
            #pragma unroll
            for (int np = 0; np < 4; np++) {
                const int n_l = ncolw + np * 16 + nInPair;
                bofs[np] = (uint32_t)(n_l * 128) +
                           (((((uint32_t)kc << 1) + bKcOff) ^ (uint32_t)(n_l & 7)) << 4);
            }
            {   // C1: e4m3(A) x e4m3(Bl*256)
                uint32_t a[4][4];
                #pragma unroll
                for (int mt = 0; mt < 4; mt++)
                    ldsm_x4(a[mt], sb + SM_A8 + aRow8 + (uint32_t)(mt * 2048) + kxA);
                uint32_t b[4][4];
                #pragma unroll
                for (int np = 0; np < 4; np++)
                    ldsm_x4(b[np], sb + SM_BL8 + bofs[np]);
                #pragma unroll
                for (int mt = 0; mt < 4; mt++)
                    #pragma unroll
                    for (int np = 0; np < 4; np++) {
                        mma_fp8(&acc[(mt * 8 + np * 2 + 0) * 4], a[mt], &b[np][0]);
                        mma_fp8(&acc[(mt * 8 + np * 2 + 1) * 4], a[mt], &b[np][2]);
                    }
            }
            {   // C2: e4m3(Al*256) x e4m3(B)
                uint32_t a[4][4];
                #pragma unroll
                for (int mt = 0; mt < 4; mt++)
                    ldsm_x4(a[mt], sb + SM_AL8 + aRow8 + (uint32_t)(mt * 2048) + kxA);
                uint32_t b[4][4];
                #pragma unroll
                for (int np = 0; np < 4; np++)
                    ldsm_x4(b[np], sb + SM_B8 + bofs[np]);
                #pragma unroll
                for (int mt = 0; mt < 4; mt++)
                    #pragma unroll
                    for (int np = 0; np < 4; np++) {
                        mma_fp8(&acc[(mt * 8 + np * 2 + 0) * 4], a[mt], &b[np][0]);
                        mma_fp8(&acc[(mt * 8 + np * 2 + 1) * 4], a[mt], &b[np][2]);
                    }
            }
        }
        #pragma unroll
        for (int i = 0; i < 128; i++) acc[i] *= (1.0f / 256.0f);

        // ---- main pass: Ah x Bh (bf16) ----
        #pragma unroll
        for (int ks = 0; ks < 8; ks++) {
            uint32_t a[4][4];
            #pragma unroll
            for (int mt = 0; mt < 4; mt++) {
                const uint32_t kx = (((uint32_t)(2 * ks) + aKcOff) ^ xr) << 4;
                ldsm_x4(a[mt], sb + SM_AH + aRowB + (uint32_t)(mt * 4096) + kx);
            }
            uint32_t b[4][4];
            #pragma unroll
            for (int np = 0; np < 4; np++) {
                const int n_l = ncolw + np * 16 + nInPair;
                const uint32_t kx = (((uint32_t)(2 * ks) + bKcOff) ^ (uint32_t)(n_l & 7)) << 4;
                ldsm_x4(b[np], sb + SM_BH + (uint32_t)(n_l * 256) + kx);
            }
            #pragma unroll
            for (int mt = 0; mt < 4; mt++)
                #pragma unroll
                for (int np = 0; np < 4; np++) {
                    mma16816(&acc[(mt * 8 + np * 2 + 0) * 4], a[mt], &b[np][0]);
                    mma16816(&acc[(mt * 8 + np * 2 + 1) * 4], a[mt], &b[np][2]);
                }
        }

        // ---- epilogue: out = scale[row] * acc + bias[col] ----
        #pragma unroll
        for (int mt = 0; mt < 4; mt++) {
            const int r0 = rowBase + mt * 16 + (lane >> 2);
            const float s0 = sscale[r0];
            const float s1 = sscale[r0 + 8];
            #pragma unroll
            for (int nt = 0; nt < 8; nt++) {
                const int col = ncolw + nt * 8 + (lane & 3) * 2;
                const float bx = sbias[col];
                const float by = sbias[col + 1];
                const float* c = &acc[(mt * 8 + nt) * 4];
                float2 o0 = make_float2(c[0] * s0 + bx, c[1] * s0 + by);
                float2 o1 = make_float2(c[2] * s1 + bx, c[3] * s1 + by);
                *reinterpret_cast<float2*>(out + (size_t)(R0 + r0) * OUT_C + col)     = o0;
                *reinterpret_cast<float2*>(out + (size_t)(R0 + r0 + 8) * OUT_C + col) = o1;
            }
        }
        __syncthreads();   // protect A smem + sscale before next tile's writes
    }
}

// ---------------- launch ----------------
extern "C" void kernel_launch(void* const* d_in, const int* in_sizes, int n_in,
                              void* d_out, int out_size) {
    (void)in_sizes; (void)n_in; (void)out_size;
    const float* H    = (const float*)d_in[0];
    const float* U    = (const float*)d_in[1];
    const float* W    = (const float*)d_in[2];
    const float* bias = (const float*)d_in[3];
    float* out = (float*)d_out;

    k_zero<<<8, 256>>>();
    k_pack1<<<SAT_NODES / 64, 512>>>(H);
    k_sat<<<32, 256>>>();
    k_pack2<<<592, 512>>>(H);
    k_fb_scale<<<512, 256>>>();               // early-exits when saturated

    cudaFuncSetAttribute(k_gemm, cudaFuncAttributeMaxDynamicSharedMemorySize, SM_TOTAL);
    k_gemm<<<148, 256, SM_TOTAL>>>(U, W, bias, out);
}

// round 13
// speedup vs baseline: 1.5642x; 1.5642x over previous
#include <cuda_runtime.h>
#include <cuda_fp16.h>
#include <stdint.h>

#define N_NODES 131072
#define N_EDGES 256
#define IN_C    128
#define OUT_C   256
#define M_TILE  128
#define N_TILES (N_NODES / M_TILE)   // 1024
#define SAT_NODES 8192

// ---------------- device scratch (no allocations allowed) ----------------
__device__ __align__(16) uint32_t g_nodeMask[N_NODES * 8];   // 4 MB (fallback only)
__device__ uint32_t g_edgeMask[N_EDGES * 8];                 // 8 KB
__device__ float    g_scale[N_NODES];
__device__ int      g_sat;

// ---------------- K0: zero edge-mask table + flag ----------------
__global__ void k_zero() {
    int i = blockIdx.x * blockDim.x + threadIdx.x;
    if (i < N_EDGES * 8) g_edgeMask[i] = 0u;
    if (i == 0) g_sat = 0;
}

// ---------------- K1: pack sample nodes -> edge masks + per-node deg ----------------
__global__ void __launch_bounds__(512) k_pack1(const float* __restrict__ H) {
    __shared__ uint32_t sEdge[N_EDGES * 8];
    const int tid  = threadIdx.x;
    const int lane = tid & 31;
    const int w    = tid & 7;

    for (int i = tid; i < N_EDGES * 8; i += 512) sEdge[i] = 0u;
    __syncthreads();

    const int node = blockIdx.x * 64 + (tid >> 3);   // 128 blocks x 64 nodes
    {
        const float4* hp = reinterpret_cast<const float4*>(
            H + (size_t)node * N_EDGES + w * 32);
        uint32_t word = 0;
        #pragma unroll
        for (int j = 0; j < 8; j++) {
            float4 f = hp[j];
            word |= (f.x >= 0.5f ? 1u : 0u) << (j * 4 + 0);
            word |= (f.y >= 0.5f ? 1u : 0u) << (j * 4 + 1);
            word |= (f.z >= 0.5f ? 1u : 0u) << (j * 4 + 2);
            word |= (f.w >= 0.5f ? 1u : 0u) << (j * 4 + 3);
        }
        g_nodeMask[node * 8 + w] = word;
        int d = __popc(word);
        d += __shfl_xor_sync(0xffffffffu, d, 1);
        d += __shfl_xor_sync(0xffffffffu, d, 2);
        d += __shfl_xor_sync(0xffffffffu, d, 4);
        if (w == 0) g_scale[node] = (float)d;     // raw deg; k_sat converts

        uint32_t wd[8];
        #pragma unroll
        for (int j = 0; j < 8; j++)
            wd[j] = __shfl_sync(0xffffffffu, word, (lane & ~7) | j);
        uint32_t m = word;
        while (m) {
            int b = __ffs(m) - 1;
            m &= m - 1;
            int e = w * 32 + b;
            #pragma unroll
            for (int j = 0; j < 8; j++) {
                uint32_t cur = sEdge[e * 8 + j];
                if ((cur & wd[j]) != wd[j]) atomicOr(&sEdge[e * 8 + j], wd[j]);
            }
        }
    }
    __syncthreads();
    for (int i = tid; i < N_EDGES * 8; i += 512) {
        uint32_t v = sEdge[i];
        if (v) atomicOr(&g_edgeMask[i], v);
    }
}

// ---------------- K2: saturation check + scale for sample nodes ----------------
__global__ void __launch_bounds__(256) k_sat() {
    __shared__ int nf;
    const int tid = threadIdx.x;
    if (tid == 0) nf = 0;
    __syncthreads();
    int bad = 0;
    for (int i = tid; i < N_EDGES * 8; i += 256)
        bad += (g_edgeMask[i] != 0xffffffffu);
    atomicAdd(&nf, bad);
    __syncthreads();
    const bool sat = (nf == 0);
    if (blockIdx.x == 0 && tid == 0) g_sat = sat ? 1 : 0;
    if (sat) {
        const int node = blockIdx.x * 256 + tid;     // 32 x 256 = 8192
        if (node < SAT_NODES) {
            float d = g_scale[node];
            g_scale[node] = (d > 0.0f) ? (1.0f + rsqrtf(d + 256.0f)) : 1.0f;
        }
    }
}

// ---------------- K3: stream remaining nodes (coalesced saturated path) ----------------
__global__ void __launch_bounds__(512) k_pack2(const float* __restrict__ H) {
    __shared__ uint32_t sEdge[N_EDGES * 8];
    const int tid  = threadIdx.x;
    const int lane = tid & 31;
    const bool sat = (g_sat != 0);

    if (sat) {
        const int wId  = tid >> 5;          // 16 warps
        const int l16  = lane & 15;
        const int half = lane >> 4;
        for (int base = SAT_NODES + blockIdx.x * 32; base < N_NODES;
             base += gridDim.x * 32) {
            const int node = base + wId * 2 + half;
            int cnt = 0;
            if (node < N_NODES) {
                const float4* hp = reinterpret_cast<const float4*>(
                    H + (size_t)node * N_EDGES) + l16;
                const float4 v0 = hp[0];
                const float4 v1 = hp[16];
                const float4 v2 = hp[32];
                const float4 v3 = hp[48];
                cnt  = (v0.x >= 0.5f) + (v0.y >= 0.5f) + (v0.z >= 0.5f) + (v0.w >= 0.5f);
                cnt += (v1.x >= 0.5f) + (v1.y >= 0.5f) + (v1.z >= 0.5f) + (v1.w >= 0.5f);
                cnt += (v2.x >= 0.5f) + (v2.y >= 0.5f) + (v2.z >= 0.5f) + (v2.w >= 0.5f);
                cnt += (v3.x >= 0.5f) + (v3.y >= 0.5f) + (v3.z >= 0.5f) + (v3.w >= 0.5f);
            }
            cnt += __shfl_xor_sync(0xffffffffu, cnt, 1);
            cnt += __shfl_xor_sync(0xffffffffu, cnt, 2);
            cnt += __shfl_xor_sync(0xffffffffu, cnt, 4);
            cnt += __shfl_xor_sync(0xffffffffu, cnt, 8);
            if (l16 == 0 && node < N_NODES)
                g_scale[node] = (cnt > 0) ? (1.0f + rsqrtf((float)(cnt + 256))) : 1.0f;
        }
        return;
    }

    // ---- exact fallback (rare) ----
    const int w = tid & 7;
    for (int i = tid; i < N_EDGES * 8; i += 512) sEdge[i] = 0u;
    __syncthreads();

    for (int base = SAT_NODES + blockIdx.x * 64; base < N_NODES; base += gridDim.x * 64) {
        const int node = base + (tid >> 3);
        const float4* hp = reinterpret_cast<const float4*>(
            H + (size_t)node * N_EDGES + w * 32);
        uint32_t word = 0;
        #pragma unroll
        for (int j = 0; j < 8; j++) {
            float4 f = hp[j];
            word |= (f.x >= 0.5f ? 1u : 0u) << (j * 4 + 0);
            word |= (f.y >= 0.5f ? 1u : 0u) << (j * 4 + 1);
            word |= (f.z >= 0.5f ? 1u : 0u) << (j * 4 + 2);
            word |= (f.w >= 0.5f ? 1u : 0u) << (j * 4 + 3);
        }
        g_nodeMask[node * 8 + w] = word;
        uint32_t wd[8];
        #pragma unroll
        for (int j = 0; j < 8; j++)
            wd[j] = __shfl_sync(0xffffffffu, word, (lane & ~7) | j);
        uint32_t m = word;
        while (m) {
            int b = __ffs(m) - 1;
            m &= m - 1;
            int e = w * 32 + b;
            #pragma unroll
            for (int j = 0; j < 8; j++) {
                uint32_t cur = sEdge[e * 8 + j];
                if ((cur & wd[j]) != wd[j]) atomicOr(&sEdge[e * 8 + j], wd[j]);
            }
        }
    }
    __syncthreads();
    for (int i = tid; i < N_EDGES * 8; i += 512) {
        uint32_t v = sEdge[i];
        if (v) atomicOr(&g_edgeMask[i], v);
    }
}

// ---------------- K4 (fallback, rare): exact scale for ALL nodes ----------------
__global__ void __launch_bounds__(256) k_fb_scale() {
    if (g_sat) return;
    __shared__ uint32_t tbl[N_EDGES * 8];
    const int tid = threadIdx.x;
    for (int i = tid; i < N_EDGES * 8; i += 256) tbl[i] = g_edgeMask[i];
    __syncthreads();

    for (int node = blockIdx.x * 256 + tid; node < N_NODES; node += gridDim.x * 256) {
        const uint4 a = reinterpret_cast<const uint4*>(g_nodeMask)[node * 2 + 0];
        const uint4 b = reinterpret_cast<const uint4*>(g_nodeMask)[node * 2 + 1];
        uint32_t wd[8] = {a.x, a.y, a.z, a.w, b.x, b.y, b.z, b.w};
        int deg = 0;
        #pragma unroll
        for (int j = 0; j < 8; j++) deg += __popc(wd[j]);
        uint32_t acc[8] = {0, 0, 0, 0, 0, 0, 0, 0};
        if (deg) {
            bool fl = false;
            for (int w0 = 0; w0 < 8 && !fl; w0++) {
                uint32_t m = wd[w0];
                while (m) {
                    int bi = __ffs(m) - 1;
                    m &= m - 1;
                    int e = w0 * 32 + bi;
                    uint32_t allones = 0xffffffffu;
                    #pragma unroll
                    for (int j = 0; j < 8; j++) {
                        acc[j] |= tbl[e * 8 + j];
                        allones &= acc[j];
                    }
                    if (allones == 0xffffffffu) { fl = true; break; }
                }
            }
        }
        int dv2 = 0;
        #pragma unroll
        for (int j = 0; j < 8; j++) dv2 += __popc(acc[j]);
        const int dv = deg + dv2;
        float s = 1.0f;
        if (dv > 0) s += rsqrtf((float)dv);
        g_scale[node] = s;
    }
}

// ---------------- K5: GEMM out = scale * (U @ W) + bias, single fp16 pass ----------------
// 512 threads = two independent 256-thread warp-groups (named barriers, R9
// structure), group g owns rows [g*64, g*64+64). fp16 mma only: half the
// tensor work, half the smem traffic vs bf16+fp8. smem = 100 KB.
#define SM_BIAS  0                       // 256 floats = 1 KB
#define SM_SCALE 1024                    // 128 floats
#define SM_AH    2048                    // 128 x 256B fp16        32 KB
#define SM_BH    (SM_AH + 32768)         // 256 x 256B fp16        64 KB
#define SM_TOTAL (SM_BH + 65536)         // 100352 bytes

__device__ __forceinline__ uint32_t sw_off(int row, int k) {     // fp16, 256B rows
    return (uint32_t)(row * 256 + ((((k >> 3) ^ (row & 7)) << 4) | ((k & 7) * 2)));
}

__device__ __forceinline__ uint32_t smem_u32(const void* p) {
    uint32_t a;
    asm("{ .reg .u64 t; cvta.to.shared.u64 t, %1; cvt.u32.u64 %0, t; }"
        : "=r"(a) : "l"(p));
    return a;
}

__device__ __forceinline__ void ldsm_x4(uint32_t* r, uint32_t addr) {
    asm volatile("ldmatrix.sync.aligned.m8n8.x4.shared.b16 {%0,%1,%2,%3}, [%4];"
                 : "=r"(r[0]), "=r"(r[1]), "=r"(r[2]), "=r"(r[3]) : "r"(addr));
}

__device__ __forceinline__ void mma16816h(float* c, const uint32_t* a, const uint32_t* b) {
    asm volatile(
        "mma.sync.aligned.m16n8k16.row.col.f32.f16.f16.f32 "
        "{%0,%1,%2,%3}, {%4,%5,%6,%7}, {%8,%9}, {%0,%1,%2,%3};"
        : "+f"(c[0]), "+f"(c[1]), "+f"(c[2]), "+f"(c[3])
        : "r"(a[0]), "r"(a[1]), "r"(a[2]), "r"(a[3]), "r"(b[0]), "r"(b[1]));
}

// 8 fp32 (row, k0..k0+7) -> fp16 smem tile (one 16B store)
__device__ __forceinline__ void convertH8(const float* v, char* smem, int row, int k0,
                                          uint32_t baseH) {
    uint32_t hi[4];
    #pragma unroll
    for (int i = 0; i < 4; i++) {
        __half2 hp = __floats2half2_rn(v[2 * i + 0], v[2 * i + 1]);
        hi[i] = *reinterpret_cast<uint32_t*>(&hp);
    }
    *reinterpret_cast<uint4*>(smem + baseH + sw_off(row, k0)) =
        make_uint4(hi[0], hi[1], hi[2], hi[3]);
}

// group-scoped prefetch: 256 threads cover 64 rows x 128 cols
__device__ __forceinline__ void prefetchA_g(const float* __restrict__ U, int R0,
                                            int gid, int gtid, float4* pf) {
    #pragma unroll
    for (int it = 0; it < 4; it++) {
        const int c  = it * 256 + gtid;
        const int m  = gid * 64 + (c >> 4);
        const int k0 = (c & 15) * 8;
        const float4* up = reinterpret_cast<const float4*>(
            U + (size_t)(R0 + m) * IN_C + k0);
        pf[2 * it + 0] = up[0];
        pf[2 * it + 1] = up[1];
    }
}

__global__ void __launch_bounds__(512, 1)
k_gemm(const float* __restrict__ U, const float* __restrict__ W,
       const float* __restrict__ bias, float* __restrict__ out)
{
    extern __shared__ char smem[];
    const uint32_t sb = smem_u32(smem);
    const int tid  = threadIdx.x;
    const int lane = tid & 31;
    const int gid  = tid >> 8;          // warp-group 0 / 1
    const int gtid = tid & 255;
    const int gwid = gtid >> 5;         // 0..7 within group
    const int wm   = gwid >> 2;         // 0..1 (32 rows each within group's 64)
    const int wn   = gwid & 3;          // 0..3 (32 cols per half)

    float* sbias  = reinterpret_cast<float*>(smem + SM_BIAS);
    float* sscale = reinterpret_cast<float*>(smem + SM_SCALE);
    if (tid < OUT_C) sbias[tid] = bias[tid];

    // ---- convert W once (all 512 threads): B[n][k] = W[k][n] -> fp16 ----
    #pragma unroll 1
    for (int it = 0; it < 8; it++) {
        const int idx = it * 512 + tid;
        const int n   = idx & 255;
        const int k0  = (idx >> 8) * 8;
        float v[8];
        #pragma unroll
        for (int i = 0; i < 8; i++) v[i] = W[(size_t)(k0 + i) * OUT_C + n];
        convertH8(v, smem, n, k0, SM_BH);
    }
    __syncthreads();    // B tile final; groups independent from here on

    const uint32_t xr = lane & 7;
    const int rowBase = gid * 64 + wm * 32;
    const uint32_t aRowB = (uint32_t)((rowBase + (lane & 15)) * 256);
    const int nInPair = (lane & 7) + ((lane >> 4) << 3);
    const uint32_t bKcOff = (lane >> 3) & 1;
    const uint32_t aKcOff = lane >> 4;

    float4 pf[8];                      // prefetched group A half-tile
    prefetchA_g(U, blockIdx.x * M_TILE, gid, gtid, pf);

    for (int tile = blockIdx.x; tile < N_TILES; tile += gridDim.x) {
        const int R0 = tile * M_TILE;

        if (gtid < 64) sscale[gid * 64 + gtid] = g_scale[R0 + gid * 64 + gtid];
        #pragma unroll
        for (int it = 0; it < 4; it++) {
            const int c  = it * 256 + gtid;
            const int m  = gid * 64 + (c >> 4);
            const int k0 = (c & 15) * 8;
            const float4 f0 = pf[2 * it + 0];
            const float4 f1 = pf[2 * it + 1];
            float v[8] = {f0.x, f0.y, f0.z, f0.w, f1.x, f1.y, f1.z, f1.w};
            convertH8(v, smem, m, k0, SM_AH);
        }
        asm volatile("bar.sync %0, %1;" :: "r"(gid + 1), "r"(256) : "memory");

        const int nxt = tile + gridDim.x;
        if (nxt < N_TILES) prefetchA_g(U, nxt * M_TILE, gid, gtid, pf);

        #pragma unroll 1
        for (int h = 0; h < 2; h++) {
            const int ncolw = h * 128 + wn * 32;
            float acc[32];
            #pragma unroll
            for (int i = 0; i < 32; i++) acc[i] = 0.0f;

            // ---- single fp16 pass: A x B ----
            #pragma unroll
            for (int ks = 0; ks < 8; ks++) {
                uint32_t a[2][4];
                #pragma unroll
                for (int mt = 0; mt < 2; mt++) {
                    const uint32_t kx = (((uint32_t)(2 * ks) + aKcOff) ^ xr) << 4;
                    ldsm_x4(a[mt], sb + SM_AH + aRowB + (uint32_t)(mt * 4096) + kx);
                }
                uint32_t b[2][4];
                #pragma unroll
                for (int np = 0; np < 2; np++) {
                    const int n_l = ncolw + np * 16 + nInPair;
                    const uint32_t kx = (((uint32_t)(2 * ks) + bKcOff) ^ (uint32_t)(n_l & 7)) << 4;
                    ldsm_x4(b[np], sb + SM_BH + (uint32_t)(n_l * 256) + kx);
                }
                #pragma unroll
                for (int mt = 0; mt < 2; mt++)
                    #pragma unroll
                    for (int np = 0; np < 2; np++) {
                        mma16816h(&acc[(mt * 4 + np * 2 + 0) * 4], a[mt], &b[np][0]);
                        mma16816h(&acc[(mt * 4 + np * 2 + 1) * 4], a[mt], &b[np][2]);
                    }
            }

            // ---- epilogue: out = scale[row] * acc + bias[col] ----
            #pragma unroll
            for (int mt = 0; mt < 2; mt++) {
                const int r0 = rowBase + mt * 16 + (lane >> 2);
                const float s0 = sscale[r0];
                const float s1 = sscale[r0 + 8];
                #pragma unroll
                for (int nt = 0; nt < 4; nt++) {
                    const int col = ncolw + nt * 8 + (lane & 3) * 2;
                    const float bx = sbias[col];
                    const float by = sbias[col + 1];
                    const float* c = &acc[(mt * 4 + nt) * 4];
                    float2 o0 = make_float2(c[0] * s0 + bx, c[1] * s0 + by);
                    float2 o1 = make_float2(c[2] * s1 + bx, c[3] * s1 + by);
                    *reinterpret_cast<float2*>(out + (size_t)(R0 + r0) * OUT_C + col)     = o0;
                    *reinterpret_cast<float2*>(out + (size_t)(R0 + r0 + 8) * OUT_C + col) = o1;
                }
            }
        }
        // protect this group's A smem + sscale before next tile's writes
        asm volatile("bar.sync %0, %1;" :: "r"(gid + 1), "r"(256) : "memory");
    }
}

// ---------------- launch ----------------
extern "C" void kernel_launch(void* const* d_in, const int* in_sizes, int n_in,
                              void* d_out, int out_size) {
    (void)in_sizes; (void)n_in; (void)out_size;
    const float* H    = (const float*)d_in[0];
    const float* U    = (const float*)d_in[1];
    const float* W    = (const float*)d_in[2];
    const float* bias = (const float*)d_in[3];
    float* out = (float*)d_out;

    k_zero<<<8, 256>>>();
    k_pack1<<<SAT_NODES / 64, 512>>>(H);
    k_sat<<<32, 256>>>();
    k_pack2<<<592, 512>>>(H);
    k_fb_scale<<<512, 256>>>();               // early-exits when saturated

    cudaFuncSetAttribute(k_gemm, cudaFuncAttributeMaxDynamicSharedMemorySize, SM_TOTAL);
    k_gemm<<<148, 512, SM_TOTAL>>>(U, W, bias, out);
}

// round 14
// speedup vs baseline: 1.7123x; 1.0947x over previous
#include <cuda_runtime.h>
#include <cuda_fp16.h>
#include <stdint.h>

#define N_NODES 131072
#define N_EDGES 256
#define IN_C    128
#define OUT_C   256
#define M_TILE  128
#define N_TILES (N_NODES / M_TILE)   // 1024
#define SAT_NODES 8192

// ---------------- device scratch (no allocations allowed) ----------------
__device__ __align__(16) uint32_t g_nodeMask[N_NODES * 8];   // 4 MB (fallback only)
__device__ uint32_t g_edgeMask[N_EDGES * 8];                 // 8 KB
__device__ float    g_scale[N_NODES];                        // fallback only
__device__ int      g_sat;

// ---------------- K0: zero edge-mask table + flag ----------------
__global__ void k_zero() {
    int i = blockIdx.x * blockDim.x + threadIdx.x;
    if (i < N_EDGES * 8) g_edgeMask[i] = 0u;
    if (i == 0) g_sat = 0;
}

// ---------------- K1: pack sample nodes -> edge masks ----------------
__global__ void __launch_bounds__(512) k_pack1(const float* __restrict__ H) {
    __shared__ uint32_t sEdge[N_EDGES * 8];
    const int tid  = threadIdx.x;
    const int lane = tid & 31;
    const int w    = tid & 7;

    for (int i = tid; i < N_EDGES * 8; i += 512) sEdge[i] = 0u;
    __syncthreads();

    const int node = blockIdx.x * 64 + (tid >> 3);   // 128 blocks x 64 nodes
    {
        const float4* hp = reinterpret_cast<const float4*>(
            H + (size_t)node * N_EDGES + w * 32);
        uint32_t word = 0;
        #pragma unroll
        for (int j = 0; j < 8; j++) {
            float4 f = hp[j];
            word |= (f.x >= 0.5f ? 1u : 0u) << (j * 4 + 0);
            word |= (f.y >= 0.5f ? 1u : 0u) << (j * 4 + 1);
            word |= (f.z >= 0.5f ? 1u : 0u) << (j * 4 + 2);
            word |= (f.w >= 0.5f ? 1u : 0u) << (j * 4 + 3);
        }
        g_nodeMask[node * 8 + w] = word;

        uint32_t wd[8];
        #pragma unroll
        for (int j = 0; j < 8; j++)
            wd[j] = __shfl_sync(0xffffffffu, word, (lane & ~7) | j);
        uint32_t m = word;
        while (m) {
            int b = __ffs(m) - 1;
            m &= m - 1;
            int e = w * 32 + b;
            #pragma unroll
            for (int j = 0; j < 8; j++) {
                uint32_t cur = sEdge[e * 8 + j];
                if ((cur & wd[j]) != wd[j]) atomicOr(&sEdge[e * 8 + j], wd[j]);
            }
        }
    }
    __syncthreads();
    for (int i = tid; i < N_EDGES * 8; i += 512) {
        uint32_t v = sEdge[i];
        if (v) atomicOr(&g_edgeMask[i], v);
    }
}

// ---------------- K2: saturation flag ----------------
__global__ void __launch_bounds__(256) k_sat() {
    __shared__ int nf;
    const int tid = threadIdx.x;
    if (tid == 0) nf = 0;
    __syncthreads();
    int bad = 0;
    for (int i = tid; i < N_EDGES * 8; i += 256)
        bad += (g_edgeMask[i] != 0xffffffffu);
    atomicAdd(&nf, bad);
    __syncthreads();
    if (tid == 0) g_sat = (nf == 0) ? 1 : 0;
}

// ---------------- K3 (fallback only): pack remaining nodes ----------------
__global__ void __launch_bounds__(512) k_pack2(const float* __restrict__ H) {
    if (g_sat) return;                          // saturated: gemm computes scales inline
    __shared__ uint32_t sEdge[N_EDGES * 8];
    const int tid  = threadIdx.x;
    const int lane = tid & 31;
    const int w    = tid & 7;

    for (int i = tid; i < N_EDGES * 8; i += 512) sEdge[i] = 0u;
    __syncthreads();

    for (int base = SAT_NODES + blockIdx.x * 64; base < N_NODES; base += gridDim.x * 64) {
        const int node = base + (tid >> 3);
        const float4* hp = reinterpret_cast<const float4*>(
            H + (size_t)node * N_EDGES + w * 32);
        uint32_t word = 0;
        #pragma unroll
        for (int j = 0; j < 8; j++) {
            float4 f = hp[j];
            word |= (f.x >= 0.5f ? 1u : 0u) << (j * 4 + 0);
            word |= (f.y >= 0.5f ? 1u : 0u) << (j * 4 + 1);
            word |= (f.z >= 0.5f ? 1u : 0u) << (j * 4 + 2);
            word |= (f.w >= 0.5f ? 1u : 0u) << (j * 4 + 3);
        }
        g_nodeMask[node * 8 + w] = word;
        uint32_t wd[8];
        #pragma unroll
        for (int j = 0; j < 8; j++)
            wd[j] = __shfl_sync(0xffffffffu, word, (lane & ~7) | j);
        uint32_t m = word;
        while (m) {
            int b = __ffs(m) - 1;
            m &= m - 1;
            int e = w * 32 + b;
            #pragma unroll
            for (int j = 0; j < 8; j++) {
                uint32_t cur = sEdge[e * 8 + j];
                if ((cur & wd[j]) != wd[j]) atomicOr(&sEdge[e * 8 + j], wd[j]);
            }
        }
    }
    __syncthreads();
    for (int i = tid; i < N_EDGES * 8; i += 512) {
        uint32_t v = sEdge[i];
        if (v) atomicOr(&g_edgeMask[i], v);
    }
}

// ---------------- K4 (fallback only): exact scale for ALL nodes ----------------
__global__ void __launch_bounds__(256) k_fb_scale() {
    if (g_sat) return;
    __shared__ uint32_t tbl[N_EDGES * 8];
    const int tid = threadIdx.x;
    for (int i = tid; i < N_EDGES * 8; i += 256) tbl[i] = g_edgeMask[i];
    __syncthreads();

    for (int node = blockIdx.x * 256 + tid; node < N_NODES; node += gridDim.x * 256) {
        const uint4 a = reinterpret_cast<const uint4*>(g_nodeMask)[node * 2 + 0];
        const uint4 b = reinterpret_cast<const uint4*>(g_nodeMask)[node * 2 + 1];
        uint32_t wd[8] = {a.x, a.y, a.z, a.w, b.x, b.y, b.z, b.w};
        int deg = 0;
        #pragma unroll
        for (int j = 0; j < 8; j++) deg += __popc(wd[j]);
        uint32_t acc[8] = {0, 0, 0, 0, 0, 0, 0, 0};
        if (deg) {
            bool fl = false;
            for (int w0 = 0; w0 < 8 && !fl; w0++) {
                uint32_t m = wd[w0];
                while (m) {
                    int bi = __ffs(m) - 1;
                    m &= m - 1;
                    int e = w0 * 32 + bi;
                    uint32_t allones = 0xffffffffu;
                    #pragma unroll
                    for (int j = 0; j < 8; j++) {
                        acc[j] |= tbl[e * 8 + j];
                        allones &= acc[j];
                    }
                    if (allones == 0xffffffffu) { fl = true; break; }
                }
            }
        }
        int dv2 = 0;
        #pragma unroll
        for (int j = 0; j < 8; j++) dv2 += __popc(acc[j]);
        const int dv = deg + dv2;
        float s = 1.0f;
        if (dv > 0) s += rsqrtf((float)dv);
        g_scale[node] = s;
    }
}

// ---------------- K5: GEMM out = scale * (U @ W) + bias, fp16, inline H scales ----------------
// 512 threads = two independent 256-thread warp-groups (named barriers),
// group g owns rows [g*64, g*64+64). Saturated path streams this tile's H
// rows inline (coalesced, 2 passes) to get dv = deg + 256 -> scale.
#define SM_BIAS  0                       // 256 floats = 1 KB
#define SM_SCALE 1024                    // 128 floats
#define SM_AH    2048                    // 128 x 256B fp16        32 KB
#define SM_BH    (SM_AH + 32768)         // 256 x 256B fp16        64 KB
#define SM_TOTAL (SM_BH + 65536)         // 100352 bytes

__device__ __forceinline__ uint32_t sw_off(int row, int k) {     // fp16, 256B rows
    return (uint32_t)(row * 256 + ((((k >> 3) ^ (row & 7)) << 4) | ((k & 7) * 2)));
}

__device__ __forceinline__ uint32_t smem_u32(const void* p) {
    uint32_t a;
    asm("{ .reg .u64 t; cvta.to.shared.u64 t, %1; cvt.u32.u64 %0, t; }"
        : "=r"(a) : "l"(p));
    return a;
}

__device__ __forceinline__ void ldsm_x4(uint32_t* r, uint32_t addr) {
    asm volatile("ldmatrix.sync.aligned.m8n8.x4.shared.b16 {%0,%1,%2,%3}, [%4];"
                 : "=r"(r[0]), "=r"(r[1]), "=r"(r[2]), "=r"(r[3]) : "r"(addr));
}

__device__ __forceinline__ void mma16816h(float* c, const uint32_t* a, const uint32_t* b) {
    asm volatile(
        "mma.sync.aligned.m16n8k16.row.col.f32.f16.f16.f32 "
        "{%0,%1,%2,%3}, {%4,%5,%6,%7}, {%8,%9}, {%0,%1,%2,%3};"
        : "+f"(c[0]), "+f"(c[1]), "+f"(c[2]), "+f"(c[3])
        : "r"(a[0]), "r"(a[1]), "r"(a[2]), "r"(a[3]), "r"(b[0]), "r"(b[1]));
}

__device__ __forceinline__ void convertH8(const float* v, char* smem, int row, int k0,
                                          uint32_t baseH) {
    uint32_t hi[4];
    #pragma unroll
    for (int i = 0; i < 4; i++) {
        __half2 hp = __floats2half2_rn(v[2 * i + 0], v[2 * i + 1]);
        hi[i] = *reinterpret_cast<uint32_t*>(&hp);
    }
    *reinterpret_cast<uint4*>(smem + baseH + sw_off(row, k0)) =
        make_uint4(hi[0], hi[1], hi[2], hi[3]);
}

// group-scoped prefetch: 256 threads cover 64 rows x 128 cols
__device__ __forceinline__ void prefetchA_g(const float* __restrict__ U, int R0,
                                            int gid, int gtid, float4* pf) {
    #pragma unroll
    for (int it = 0; it < 4; it++) {
        const int c  = it * 256 + gtid;
        const int m  = gid * 64 + (c >> 4);
        const int k0 = (c & 15) * 8;
        const float4* up = reinterpret_cast<const float4*>(
            U + (size_t)(R0 + m) * IN_C + k0);
        pf[2 * it + 0] = up[0];
        pf[2 * it + 1] = up[1];
    }
}

__device__ __forceinline__ int cnt16(const float4* hv) {
    int c = 0;
    #pragma unroll
    for (int i = 0; i < 8; i++) {
        c += (hv[i].x >= 0.5f) + (hv[i].y >= 0.5f)
           + (hv[i].z >= 0.5f) + (hv[i].w >= 0.5f);
    }
    return c;
}

__global__ void __launch_bounds__(512, 1)
k_gemm(const float* __restrict__ H, const float* __restrict__ U,
       const float* __restrict__ W, const float* __restrict__ bias,
       float* __restrict__ out)
{
    extern __shared__ char smem[];
    const uint32_t sb = smem_u32(smem);
    const int tid  = threadIdx.x;
    const int lane = tid & 31;
    const int gid  = tid >> 8;          // warp-group 0 / 1
    const int gtid = tid & 255;
    const int gwid = gtid >> 5;         // 0..7 within group
    const int wm   = gwid >> 2;         // 0..1 (32 rows each within group's 64)
    const int wn   = gwid & 3;          // 0..3 (32 cols per half)

    float* sbias  = reinterpret_cast<float*>(smem + SM_BIAS);
    float* sscale = reinterpret_cast<float*>(smem + SM_SCALE);
    if (tid < OUT_C) sbias[tid] = bias[tid];
    const bool sat = (g_sat != 0);

    // ---- convert W once (all 512 threads): B[n][k] = W[k][n] -> fp16 ----
    #pragma unroll 1
    for (int it = 0; it < 8; it++) {
        const int idx = it * 512 + tid;
        const int n   = idx & 255;
        const int k0  = (idx >> 8) * 8;
        float v[8];
        #pragma unroll
        for (int i = 0; i < 8; i++) v[i] = W[(size_t)(k0 + i) * OUT_C + n];
        convertH8(v, smem, n, k0, SM_BH);
    }
    __syncthreads();    // B tile final; groups independent from here on

    const uint32_t xr = lane & 7;
    const int rowBase = gid * 64 + wm * 32;
    const uint32_t aRowB = (uint32_t)((rowBase + (lane & 15)) * 256);
    const int nInPair = (lane & 7) + ((lane >> 4) << 3);
    const uint32_t bKcOff = (lane >> 3) & 1;
    const uint32_t aKcOff = lane >> 4;

    // inline-H mapping: warp covers 4 rows/pass; lanes grouped 8 per row
    const int l8    = lane & 7;
    const int hRowL = gid * 64 + gwid * 4 + (lane >> 3);   // local tile row, pass adds 32

    float4 pf[8];                      // prefetched group A half-tile
    prefetchA_g(U, blockIdx.x * M_TILE, gid, gtid, pf);

    for (int tile = blockIdx.x; tile < N_TILES; tile += gridDim.x) {
        const int R0 = tile * M_TILE;

        if (sat) {
            // pass 1: H rows [hRowL, +32)
            float4 hv[8];
            {
                const float4* hp = reinterpret_cast<const float4*>(
                    H + (size_t)(R0 + hRowL) * N_EDGES) + l8;
                #pragma unroll
                for (int j = 0; j < 8; j++) hv[j] = hp[j * 8];
            }
            // convert first half of A while H pass-1 is in flight
            #pragma unroll
            for (int it = 0; it < 2; it++) {
                const int c  = it * 256 + gtid;
                const int m  = gid * 64 + (c >> 4);
                const int k0 = (c & 15) * 8;
                const float4 f0 = pf[2 * it + 0];
                const float4 f1 = pf[2 * it + 1];
                float v[8] = {f0.x, f0.y, f0.z, f0.w, f1.x, f1.y, f1.z, f1.w};
                convertH8(v, smem, m, k0, SM_AH);
            }
            {
                int c = cnt16(hv);
                c += __shfl_xor_sync(0xffffffffu, c, 1);
                c += __shfl_xor_sync(0xffffffffu, c, 2);
                c += __shfl_xor_sync(0xffffffffu, c, 4);
                if (l8 == 0)
                    sscale[hRowL] = (c > 0) ? (1.0f + rsqrtf((float)(c + 256))) : 1.0f;
            }
            // pass 2: H rows [hRowL+32, +32)
            {
                const float4* hp = reinterpret_cast<const float4*>(
                    H + (size_t)(R0 + hRowL + 32) * N_EDGES) + l8;
                #pragma unroll
                for (int j = 0; j < 8; j++) hv[j] = hp[j * 8];
            }
            #pragma unroll
            for (int it = 2; it < 4; it++) {
                const int c  = it * 256 + gtid;
                const int m  = gid * 64 + (c >> 4);
                const int k0 = (c & 15) * 8;
                const float4 f0 = pf[2 * it + 0];
                const float4 f1 = pf[2 * it + 1];
                float v[8] = {f0.x, f0.y, f0.z, f0.w, f1.x, f1.y, f1.z, f1.w};
                convertH8(v, smem, m, k0, SM_AH);
            }
            {
                int c = cnt16(hv);
                c += __shfl_xor_sync(0xffffffffu, c, 1);
                c += __shfl_xor_sync(0xffffffffu, c, 2);
                c += __shfl_xor_sync(0xffffffffu, c, 4);
                if (l8 == 0)
                    sscale[hRowL + 32] = (c > 0) ? (1.0f + rsqrtf((float)(c + 256))) : 1.0f;
            }
        } else {
            if (gtid < 64) sscale[gid * 64 + gtid] = g_scale[R0 + gid * 64 + gtid];
            #pragma unroll
            for (int it = 0; it < 4; it++) {
                const int c  = it * 256 + gtid;
                const int m  = gid * 64 + (c >> 4);
                const int k0 = (c & 15) * 8;
                const float4 f0 = pf[2 * it + 0];
                const float4 f1 = pf[2 * it + 1];
                float v[8] = {f0.x, f0.y, f0.z, f0.w, f1.x, f1.y, f1.z, f1.w};
                convertH8(v, smem, m, k0, SM_AH);
            }
        }
        asm volatile("bar.sync %0, %1;" :: "r"(gid + 1), "r"(256) : "memory");

        const int nxt = tile + gridDim.x;
        if (nxt < N_TILES) prefetchA_g(U, nxt * M_TILE, gid, gtid, pf);

        #pragma unroll 1
        for (int h = 0; h < 2; h++) {
            const int ncolw = h * 128 + wn * 32;
            float acc[32];
            #pragma unroll
            for (int i = 0; i < 32; i++) acc[i] = 0.0f;

            // ---- single fp16 pass: A x B ----
            #pragma unroll
            for (int ks = 0; ks < 8; ks++) {
                uint32_t a[2][4];
                #pragma unroll
                for (int mt = 0; mt < 2; mt++) {
                    const uint32_t kx = (((uint32_t)(2 * ks) + aKcOff) ^ xr) << 4;
                    ldsm_x4(a[mt], sb + SM_AH + aRowB + (uint32_t)(mt * 4096) + kx);
                }
                uint32_t b[2][4];
                #pragma unroll
                for (int np = 0; np < 2; np++) {
                    const int n_l = ncolw + np * 16 + nInPair;
                    const uint32_t kx = (((uint32_t)(2 * ks) + bKcOff) ^ (uint32_t)(n_l & 7)) << 4;
                    ldsm_x4(b[np], sb + SM_BH + (uint32_t)(n_l * 256) + kx);
                }
                #pragma unroll
                for (int mt = 0; mt < 2; mt++)
                    #pragma unroll
                    for (int np = 0; np < 2; np++) {
                        mma16816h(&acc[(mt * 4 + np * 2 + 0) * 4], a[mt], &b[np][0]);
                        mma16816h(&acc[(mt * 4 + np * 2 + 1) * 4], a[mt], &b[np][2]);
                    }
            }

            // ---- epilogue: out = scale[row] * acc + bias[col] ----
            #pragma unroll
            for (int mt = 0; mt < 2; mt++) {
                const int r0 = rowBase + mt * 16 + (lane >> 2);
                const float s0 = sscale[r0];
                const float s1 = sscale[r0 + 8];
                #pragma unroll
                for (int nt = 0; nt < 4; nt++) {
                    const int col = ncolw + nt * 8 + (lane & 3) * 2;
                    const float bx = sbias[col];
                    const float by = sbias[col + 1];
                    const float* c = &acc[(mt * 4 + nt) * 4];
                    float2 o0 = make_float2(c[0] * s0 + bx, c[1] * s0 + by);
                    float2 o1 = make_float2(c[2] * s1 + bx, c[3] * s1 + by);
                    *reinterpret_cast<float2*>(out + (size_t)(R0 + r0) * OUT_C + col)     = o0;
                    *reinterpret_cast<float2*>(out + (size_t)(R0 + r0 + 8) * OUT_C + col) = o1;
                }
            }
        }
        // protect this group's A smem + sscale before next tile's writes
        asm volatile("bar.sync %0, %1;" :: "r"(gid + 1), "r"(256) : "memory");
    }
}

// ---------------- launch ----------------
extern "C" void kernel_launch(void* const* d_in, const int* in_sizes, int n_in,
                              void* d_out, int out_size) {
    (void)in_sizes; (void)n_in; (void)out_size;
    const float* H    = (const float*)d_in[0];
    const float* U    = (const float*)d_in[1];
    const float* W    = (const float*)d_in[2];
    const float* bias = (const float*)d_in[3];
    float* out = (float*)d_out;

    k_zero<<<8, 256>>>();
    k_pack1<<<SAT_NODES / 64, 512>>>(H);
    k_sat<<<32, 256>>>();
    k_pack2<<<592, 512>>>(H);                 // fallback only; early-exits when saturated
    k_fb_scale<<<512, 256>>>();               // fallback only

    cudaFuncSetAttribute(k_gemm, cudaFuncAttributeMaxDynamicSharedMemorySize, SM_TOTAL);
    k_gemm<<<148, 512, SM_TOTAL>>>(H, U, W, bias, out);
}

// round 15
// speedup vs baseline: 1.7204x; 1.0047x over previous
#include <cuda_runtime.h>
#include <cuda_fp16.h>
#include <stdint.h>

#define N_NODES 131072
#define N_EDGES 256
#define IN_C    128
#define OUT_C   256
#define M_TILE  128
#define N_TILES (N_NODES / M_TILE)   // 1024
#define SAT_NODES 8192
#define PACK1_BLOCKS (SAT_NODES / 64)  // 128

// ---------------- device scratch (no allocations allowed) ----------------
__device__ __align__(16) uint32_t g_nodeMask[N_NODES * 8];   // fallback only
__device__ uint32_t g_edgeMask[N_EDGES * 8];                 // 8 KB
__device__ float    g_scale[N_NODES];                        // fallback only
__device__ int      g_sat;
__device__ int      g_done;

// ---------------- K0: zero edge-mask table + flags ----------------
__global__ void k_zero() {
    int i = blockIdx.x * blockDim.x + threadIdx.x;
    if (i < N_EDGES * 8) g_edgeMask[i] = 0u;
    if (i == 0) { g_sat = 0; g_done = 0; }
}

// ---------------- K1: pack sample nodes -> edge masks; last block sets g_sat ----------------
// Coalesced: warp = 2 rows (lanes 0-15 row A, 16-31 row B), lane reads 4
// contiguous float4 (nL=4/LDG). Words assembled via shfl nibble-gather.
__global__ void __launch_bounds__(512) k_pack1(const float* __restrict__ H) {
    __shared__ uint32_t sEdge[N_EDGES * 8];
    const int tid  = threadIdx.x;
    const int lane = tid & 31;
    const int wId  = tid >> 5;          // 16 warps
    const int l16  = lane & 15;
    const int half = lane >> 4;

    for (int i = tid; i < N_EDGES * 8; i += 512) sEdge[i] = 0u;
    __syncthreads();

    #pragma unroll
    for (int s = 0; s < 2; s++) {       // 2 sweeps x 32 rows = 64 nodes/block
        const int node = blockIdx.x * 64 + s * 32 + wId * 2 + half;

        // coalesced load: lane covers float4 indices l16, l16+16, l16+32, l16+48
        const float4* hp = reinterpret_cast<const float4*>(
            H + (size_t)node * N_EDGES) + l16;
        uint32_t pack = 0;              // 4 nibbles, one per load j
        #pragma unroll
        for (int j = 0; j < 4; j++) {
            const float4 f = hp[j * 16];
            uint32_t nib = (f.x >= 0.5f ? 1u : 0u)
                         | (f.y >= 0.5f ? 2u : 0u)
                         | (f.z >= 0.5f ? 4u : 0u)
                         | (f.w >= 0.5f ? 8u : 0u);
            pack |= nib << (4 * j);
        }
        // assemble word w = l16 (for l16 < 8): edges [32w, 32w+32)
        // source lanes: same half, l16 = (w&1)*8 + i; nibble index j = w>>1
        uint32_t word = 0;
        {
            const int w = l16 & 7;      // assembling lanes use their own index
            const int j = w >> 1;
            const int srcBase = half * 16 + (w & 1) * 8;
            #pragma unroll
            for (int i = 0; i < 8; i++) {
                uint32_t p = __shfl_sync(0xffffffffu, pack, srcBase + i);
                word |= ((p >> (4 * j)) & 0xFu) << (4 * i);
            }
        }
        const bool active = (l16 < 8);
        if (active) g_nodeMask[node * 8 + l16] = word;

        // gather this node's full 8-word mask (lanes half*16 + 0..7)
        uint32_t wd[8];
        #pragma unroll
        for (int j = 0; j < 8; j++)
            wd[j] = __shfl_sync(0xffffffffu, word, half * 16 + j);

        if (active) {
            uint32_t m = word;
            while (m) {
                int b = __ffs(m) - 1;
                m &= m - 1;
                int e = (l16 & 7) * 32 + b;
                #pragma unroll
                for (int j = 0; j < 8; j++) {
                    uint32_t cur = sEdge[e * 8 + j];
                    if ((cur & wd[j]) != wd[j]) atomicOr(&sEdge[e * 8 + j], wd[j]);
                }
            }
        }
    }
    __syncthreads();
    for (int i = tid; i < N_EDGES * 8; i += 512) {
        uint32_t v = sEdge[i];
        if (v) atomicOr(&g_edgeMask[i], v);
    }

    // ---- last block checks saturation (folded k_sat) ----
    __shared__ int sTicket;
    __threadfence();
    __syncthreads();
    if (tid == 0) sTicket = atomicAdd(&g_done, 1);
    __syncthreads();
    if (sTicket == PACK1_BLOCKS - 1) {
        __shared__ int nf;
        if (tid == 0) nf = 0;
        __syncthreads();
        int bad = 0;
        for (int i = tid; i < N_EDGES * 8; i += 512)
            bad += (g_edgeMask[i] != 0xffffffffu);
        atomicAdd(&nf, bad);
        __syncthreads();
        if (tid == 0) g_sat = (nf == 0) ? 1 : 0;
    }
}

// ---------------- K3 (fallback only): pack remaining nodes ----------------
__global__ void __launch_bounds__(512) k_pack2(const float* __restrict__ H) {
    if (g_sat) return;                          // saturated: gemm computes scales inline
    __shared__ uint32_t sEdge[N_EDGES * 8];
    const int tid  = threadIdx.x;
    const int lane = tid & 31;
    const int w    = tid & 7;

    for (int i = tid; i < N_EDGES * 8; i += 512) sEdge[i] = 0u;
    __syncthreads();

    for (int base = SAT_NODES + blockIdx.x * 64; base < N_NODES; base += gridDim.x * 64) {
        const int node = base + (tid >> 3);
        const float4* hp = reinterpret_cast<const float4*>(
            H + (size_t)node * N_EDGES + w * 32);
        uint32_t word = 0;
        #pragma unroll
        for (int j = 0; j < 8; j++) {
            float4 f = hp[j];
            word |= (f.x >= 0.5f ? 1u : 0u) << (j * 4 + 0);
            word |= (f.y >= 0.5f ? 1u : 0u) << (j * 4 + 1);
            word |= (f.z >= 0.5f ? 1u : 0u) << (j * 4 + 2);
            word |= (f.w >= 0.5f ? 1u : 0u) << (j * 4 + 3);
        }
        g_nodeMask[node * 8 + w] = word;
        uint32_t wd[8];
        #pragma unroll
        for (int j = 0; j < 8; j++)
            wd[j] = __shfl_sync(0xffffffffu, word, (lane & ~7) | j);
        uint32_t m = word;
        while (m) {
            int b = __ffs(m) - 1;
            m &= m - 1;
            int e = w * 32 + b;
            #pragma unroll
            for (int j = 0; j < 8; j++) {
                uint32_t cur = sEdge[e * 8 + j];
                if ((cur & wd[j]) != wd[j]) atomicOr(&sEdge[e * 8 + j], wd[j]);
            }
        }
    }
    __syncthreads();
    for (int i = tid; i < N_EDGES * 8; i += 512) {
        uint32_t v = sEdge[i];
        if (v) atomicOr(&g_edgeMask[i], v);
    }
}

// ---------------- K4 (fallback only): exact scale for ALL nodes ----------------
__global__ void __launch_bounds__(256) k_fb_scale() {
    if (g_sat) return;
    __shared__ uint32_t tbl[N_EDGES * 8];
    const int tid = threadIdx.x;
    for (int i = tid; i < N_EDGES * 8; i += 256) tbl[i] = g_edgeMask[i];
    __syncthreads();

    for (int node = blockIdx.x * 256 + tid; node < N_NODES; node += gridDim.x * 256) {
        const uint4 a = reinterpret_cast<const uint4*>(g_nodeMask)[node * 2 + 0];
        const uint4 b = reinterpret_cast<const uint4*>(g_nodeMask)[node * 2 + 1];
        uint32_t wd[8] = {a.x, a.y, a.z, a.w, b.x, b.y, b.z, b.w};
        int deg = 0;
        #pragma unroll
        for (int j = 0; j < 8; j++) deg += __popc(wd[j]);
        uint32_t acc[8] = {0, 0, 0, 0, 0, 0, 0, 0};
        if (deg) {
            bool fl = false;
            for (int w0 = 0; w0 < 8 && !fl; w0++) {
                uint32_t m = wd[w0];
                while (m) {
                    int bi = __ffs(m) - 1;
                    m &= m - 1;
                    int e = w0 * 32 + bi;
                    uint32_t allones = 0xffffffffu;
                    #pragma unroll
                    for (int j = 0; j < 8; j++) {
                        acc[j] |= tbl[e * 8 + j];
                        allones &= acc[j];
                    }
                    if (allones == 0xffffffffu) { fl = true; break; }
                }
            }
        }
        int dv2 = 0;
        #pragma unroll
        for (int j = 0; j < 8; j++) dv2 += __popc(acc[j]);
        const int dv = deg + dv2;
        float s = 1.0f;
        if (dv > 0) s += rsqrtf((float)dv);
        g_scale[node] = s;
    }
}

// ---------------- K5: GEMM out = scale * (U @ W) + bias, fp16, inline H scales ----------------
#define SM_BIAS  0                       // 256 floats = 1 KB
#define SM_SCALE 1024                    // 128 floats
#define SM_AH    2048                    // 128 x 256B fp16        32 KB
#define SM_BH    (SM_AH + 32768)         // 256 x 256B fp16        64 KB
#define SM_TOTAL (SM_BH + 65536)         // 100352 bytes

__device__ __forceinline__ uint32_t sw_off(int row, int k) {     // fp16, 256B rows
    return (uint32_t)(row * 256 + ((((k >> 3) ^ (row & 7)) << 4) | ((k & 7) * 2)));
}

__device__ __forceinline__ uint32_t smem_u32(const void* p) {
    uint32_t a;
    asm("{ .reg .u64 t; cvta.to.shared.u64 t, %1; cvt.u32.u64 %0, t; }"
        : "=r"(a) : "l"(p));
    return a;
}

__device__ __forceinline__ void ldsm_x4(uint32_t* r, uint32_t addr) {
    asm volatile("ldmatrix.sync.aligned.m8n8.x4.shared.b16 {%0,%1,%2,%3}, [%4];"
                 : "=r"(r[0]), "=r"(r[1]), "=r"(r[2]), "=r"(r[3]) : "r"(addr));
}

__device__ __forceinline__ void mma16816h(float* c, const uint32_t* a, const uint32_t* b) {
    asm volatile(
        "mma.sync.aligned.m16n8k16.row.col.f32.f16.f16.f32 "
        "{%0,%1,%2,%3}, {%4,%5,%6,%7}, {%8,%9}, {%0,%1,%2,%3};"
        : "+f"(c[0]), "+f"(c[1]), "+f"(c[2]), "+f"(c[3])
        : "r"(a[0]), "r"(a[1]), "r"(a[2]), "r"(a[3]), "r"(b[0]), "r"(b[1]));
}

__device__ __forceinline__ void convertH8(const float* v, char* smem, int row, int k0,
                                          uint32_t baseH) {
    uint32_t hi[4];
    #pragma unroll
    for (int i = 0; i < 4; i++) {
        __half2 hp = __floats2half2_rn(v[2 * i + 0], v[2 * i + 1]);
        hi[i] = *reinterpret_cast<uint32_t*>(&hp);
    }
    *reinterpret_cast<uint4*>(smem + baseH + sw_off(row, k0)) =
        make_uint4(hi[0], hi[1], hi[2], hi[3]);
}

// group-scoped prefetch: 256 threads cover 64 rows x 128 cols
__device__ __forceinline__ void prefetchA_g(const float* __restrict__ U, int R0,
                                            int gid, int gtid, float4* pf) {
    #pragma unroll
    for (int it = 0; it < 4; it++) {
        const int c  = it * 256 + gtid;
        const int m  = gid * 64 + (c >> 4);
        const int k0 = (c & 15) * 8;
        const float4* up = reinterpret_cast<const float4*>(
            U + (size_t)(R0 + m) * IN_C + k0);
        pf[2 * it + 0] = up[0];
        pf[2 * it + 1] = up[1];
    }
}

__device__ __forceinline__ int cnt16(const float4* hv) {
    int c = 0;
    #pragma unroll
    for (int i = 0; i < 8; i++) {
        c += (hv[i].x >= 0.5f) + (hv[i].y >= 0.5f)
           + (hv[i].z >= 0.5f) + (hv[i].w >= 0.5f);
    }
    return c;
}

__global__ void __launch_bounds__(512, 1)
k_gemm(const float* __restrict__ H, const float* __restrict__ U,
       const float* __restrict__ W, const float* __restrict__ bias,
       float* __restrict__ out)
{
    extern __shared__ char smem[];
    const uint32_t sb = smem_u32(smem);
    const int tid  = threadIdx.x;
    const int lane = tid & 31;
    const int gid  = tid >> 8;          // warp-group 0 / 1
    const int gtid = tid & 255;
    const int gwid = gtid >> 5;         // 0..7 within group
    const int wm   = gwid >> 2;         // 0..1 (32 rows each within group's 64)
    const int wn   = gwid & 3;          // 0..3 (32 cols per half)

    float* sbias  = reinterpret_cast<float*>(smem + SM_BIAS);
    float* sscale = reinterpret_cast<float*>(smem + SM_SCALE);
    if (tid < OUT_C) sbias[tid] = bias[tid];
    const bool sat = (g_sat != 0);

    // ---- convert W once (all 512 threads): B[n][k] = W[k][n] -> fp16 ----
    #pragma unroll 1
    for (int it = 0; it < 8; it++) {
        const int idx = it * 512 + tid;
        const int n   = idx & 255;
        const int k0  = (idx >> 8) * 8;
        float v[8];
        #pragma unroll
        for (int i = 0; i < 8; i++) v[i] = W[(size_t)(k0 + i) * OUT_C + n];
        convertH8(v, smem, n, k0, SM_BH);
    }
    __syncthreads();    // B tile final; groups independent from here on

    const uint32_t xr = lane & 7;
    const int rowBase = gid * 64 + wm * 32;
    const uint32_t aRowB = (uint32_t)((rowBase + (lane & 15)) * 256);
    const int nInPair = (lane & 7) + ((lane >> 4) << 3);
    const uint32_t bKcOff = (lane >> 3) & 1;
    const uint32_t aKcOff = lane >> 4;

    // inline-H mapping: warp covers 4 rows/pass; lanes grouped 8 per row
    const int l8    = lane & 7;
    const int hRowL = gid * 64 + gwid * 4 + (lane >> 3);   // local tile row, pass adds 32

    float4 pf[8];                      // prefetched group A half-tile
    prefetchA_g(U, blockIdx.x * M_TILE, gid, gtid, pf);

    for (int tile = blockIdx.x; tile < N_TILES; tile += gridDim.x) {
        const int R0 = tile * M_TILE;

        if (sat) {
            // pass 1: H rows [hRowL, +32)
            float4 hv[8];
            {
                const float4* hp = reinterpret_cast<const float4*>(
                    H + (size_t)(R0 + hRowL) * N_EDGES) + l8;
                #pragma unroll
                for (int j = 0; j < 8; j++) hv[j] = hp[j * 8];
            }
            #pragma unroll
            for (int it = 0; it < 2; it++) {
                const int c  = it * 256 + gtid;
                const int m  = gid * 64 + (c >> 4);
                const int k0 = (c & 15) * 8;
                const float4 f0 = pf[2 * it + 0];
                const float4 f1 = pf[2 * it + 1];
                float v[8] = {f0.x, f0.y, f0.z, f0.w, f1.x, f1.y, f1.z, f1.w};
                convertH8(v, smem, m, k0, SM_AH);
            }
            {
                int c = cnt16(hv);
                c += __shfl_xor_sync(0xffffffffu, c, 1);
                c += __shfl_xor_sync(0xffffffffu, c, 2);
                c += __shfl_xor_sync(0xffffffffu, c, 4);
                if (l8 == 0)
                    sscale[hRowL] = (c > 0) ? (1.0f + rsqrtf((float)(c + 256))) : 1.0f;
            }
            // pass 2: H rows [hRowL+32, +32)
            {
                const float4* hp = reinterpret_cast<const float4*>(
                    H + (size_t)(R0 + hRowL + 32) * N_EDGES) + l8;
                #pragma unroll
                for (int j = 0; j < 8; j++) hv[j] = hp[j * 8];
            }
            #pragma unroll
            for (int it = 2; it < 4; it++) {
                const int c  = it * 256 + gtid;
                const int m  = gid * 64 + (c >> 4);
                const int k0 = (c & 15) * 8;
                const float4 f0 = pf[2 * it + 0];
                const float4 f1 = pf[2 * it + 1];
                float v[8] = {f0.x, f0.y, f0.z, f0.w, f1.x, f1.y, f1.z, f1.w};
                convertH8(v, smem, m, k0, SM_AH);
            }
            {
                int c = cnt16(hv);
                c += __shfl_xor_sync(0xffffffffu, c, 1);
                c += __shfl_xor_sync(0xffffffffu, c, 2);
                c += __shfl_xor_sync(0xffffffffu, c, 4);
                if (l8 == 0)
                    sscale[hRowL + 32] = (c > 0) ? (1.0f + rsqrtf((float)(c + 256))) : 1.0f;
            }
        } else {
            if (gtid < 64) sscale[gid * 64 + gtid] = g_scale[R0 + gid * 64 + gtid];
            #pragma unroll
            for (int it = 0; it < 4; it++) {
                const int c  = it * 256 + gtid;
                const int m  = gid * 64 + (c >> 4);
                const int k0 = (c & 15) * 8;
                const float4 f0 = pf[2 * it + 0];
                const float4 f1 = pf[2 * it + 1];
                float v[8] = {f0.x, f0.y, f0.z, f0.w, f1.x, f1.y, f1.z, f1.w};
                convertH8(v, smem, m, k0, SM_AH);
            }
        }
        asm volatile("bar.sync %0, %1;" :: "r"(gid + 1), "r"(256) : "memory");

        const int nxt = tile + gridDim.x;
        if (nxt < N_TILES) prefetchA_g(U, nxt * M_TILE, gid, gtid, pf);

        #pragma unroll 1
        for (int h = 0; h < 2; h++) {
            const int ncolw = h * 128 + wn * 32;
            float acc[32];
            #pragma unroll
            for (int i = 0; i < 32; i++) acc[i] = 0.0f;

            // ---- single fp16 pass: A x B ----
            #pragma unroll
            for (int ks = 0; ks < 8; ks++) {
                uint32_t a[2][4];
                #pragma unroll
                for (int mt = 0; mt < 2; mt++) {
                    const uint32_t kx = (((uint32_t)(2 * ks) + aKcOff) ^ xr) << 4;
                    ldsm_x4(a[mt], sb + SM_AH + aRowB + (uint32_t)(mt * 4096) + kx);
                }
                uint32_t b[2][4];
                #pragma unroll
                for (int np = 0; np < 2; np++) {
                    const int n_l = ncolw + np * 16 + nInPair;
                    const uint32_t kx = (((uint32_t)(2 * ks) + bKcOff) ^ (uint32_t)(n_l & 7)) << 4;
                    ldsm_x4(b[np], sb + SM_BH + (uint32_t)(n_l * 256) + kx);
                }
                #pragma unroll
                for (int mt = 0; mt < 2; mt++)
                    #pragma unroll
                    for (int np = 0; np < 2; np++) {
                        mma16816h(&acc[(mt * 4 + np * 2 + 0) * 4], a[mt], &b[np][0]);
                        mma16816h(&acc[(mt * 4 + np * 2 + 1) * 4], a[mt], &b[np][2]);
                    }
            }

            // ---- epilogue: out = scale[row] * acc + bias[col] ----
            #pragma unroll
            for (int mt = 0; mt < 2; mt++) {
                const int r0 = rowBase + mt * 16 + (lane >> 2);
                const float s0 = sscale[r0];
                const float s1 = sscale[r0 + 8];
                #pragma unroll
                for (int nt = 0; nt < 4; nt++) {
                    const int col = ncolw + nt * 8 + (lane & 3) * 2;
                    const float bx = sbias[col];
                    const float by = sbias[col + 1];
                    const float* c = &acc[(mt * 4 + nt) * 4];
                    float2 o0 = make_float2(c[0] * s0 + bx, c[1] * s0 + by);
                    float2 o1 = make_float2(c[2] * s1 + bx, c[3] * s1 + by);
                    *reinterpret_cast<float2*>(out + (size_t)(R0 + r0) * OUT_C + col)     = o0;
                    *reinterpret_cast<float2*>(out + (size_t)(R0 + r0 + 8) * OUT_C + col) = o1;
                }
            }
        }
        // protect this group's A smem + sscale before next tile's writes
        asm volatile("bar.sync %0, %1;" :: "r"(gid + 1), "r"(256) : "memory");
    }
}

// ---------------- launch ----------------
extern "C" void kernel_launch(void* const* d_in, const int* in_sizes, int n_in,
                              void* d_out, int out_size) {
    (void)in_sizes; (void)n_in; (void)out_size;
    const float* H    = (const float*)d_in[0];
    const float* U    = (const float*)d_in[1];
    const float* W    = (const float*)d_in[2];
    const float* bias = (const float*)d_in[3];
    float* out = (float*)d_out;

    k_zero<<<8, 256>>>();
    k_pack1<<<PACK1_BLOCKS, 512>>>(H);        // includes saturation check
    k_pack2<<<148, 512>>>(H);                 // fallback only; early-exits when saturated
    k_fb_scale<<<148, 256>>>();               // fallback only

    cudaFuncSetAttribute(k_gemm, cudaFuncAttributeMaxDynamicSharedMemorySize, SM_TOTAL);
    k_gemm<<<148, 512, SM_TOTAL>>>(H, U, W, bias, out);
}

// round 16
// speedup vs baseline: 1.8336x; 1.0658x over previous
#include <cuda_runtime.h>
#include <cuda_fp16.h>
#include <stdint.h>

#define N_NODES 131072
#define N_EDGES 256
#define IN_C    128
#define OUT_C   256
#define M_TILE  128
#define N_TILES (N_NODES / M_TILE)   // 1024
#define SAT_NODES 8192
#define PACK1_BLOCKS (SAT_NODES / 64)  // 128

// ---------------- device scratch (no allocations allowed) ----------------
__device__ __align__(16) uint32_t g_nodeMask[N_NODES * 8];   // fallback only
__device__ uint32_t g_edgeMask[N_EDGES * 8];   // zero-init; reset by k_gemm tail
__device__ float    g_scale[N_NODES];          // fallback only
__device__ int      g_sat;                     // overwritten by k_pack1 each run
__device__ int      g_done;                    // zero-init; reset by k_gemm tail

__device__ __forceinline__ void spin_until(int target) {
    // all participating blocks are co-resident (one wave) -> deadlock-free
    if (threadIdx.x == 0) {
        while (atomicAdd(&g_done, 0) < target) { }
    }
    __syncthreads();
    __threadfence();
}

// ---------------- K1: full prepass in one launch ----------------
// Phase A: coalesced pack of SAT_NODES sample -> edge masks (+nodeMask store).
// Rendezvous; every block re-checks saturation. If saturated: done (g_sat=1).
// If not: Phase B full pack of remaining nodes, rendezvous, exact scale.
__global__ void __launch_bounds__(512) k_pack1(const float* __restrict__ H) {
    __shared__ uint32_t sEdge[N_EDGES * 8];
    __shared__ int nf;
    const int tid  = threadIdx.x;
    const int lane = tid & 31;
    const int wId  = tid >> 5;          // 16 warps
    const int l16  = lane & 15;
    const int half = lane >> 4;

    for (int i = tid; i < N_EDGES * 8; i += 512) sEdge[i] = 0u;
    __syncthreads();

    // ---- Phase A: sample pack (coalesced; warp = 2 rows) ----
    #pragma unroll
    for (int s = 0; s < 2; s++) {       // 2 sweeps x 32 rows = 64 nodes/block
        const int node = blockIdx.x * 64 + s * 32 + wId * 2 + half;

        const float4* hp = reinterpret_cast<const float4*>(
            H + (size_t)node * N_EDGES) + l16;
        uint32_t pack = 0;              // 4 nibbles, one per load j
        #pragma unroll
        for (int j = 0; j < 4; j++) {
            const float4 f = hp[j * 16];
            uint32_t nib = (f.x >= 0.5f ? 1u : 0u)
                         | (f.y >= 0.5f ? 2u : 0u)
                         | (f.z >= 0.5f ? 4u : 0u)
                         | (f.w >= 0.5f ? 8u : 0u);
            pack |= nib << (4 * j);
        }
        uint32_t word = 0;
        {
            const int w = l16 & 7;
            const int j = w >> 1;
            const int srcBase = half * 16 + (w & 1) * 8;
            #pragma unroll
            for (int i = 0; i < 8; i++) {
                uint32_t p = __shfl_sync(0xffffffffu, pack, srcBase + i);
                word |= ((p >> (4 * j)) & 0xFu) << (4 * i);
            }
        }
        const bool active = (l16 < 8);
        if (active) g_nodeMask[node * 8 + l16] = word;

        uint32_t wd[8];
        #pragma unroll
        for (int j = 0; j < 8; j++)
            wd[j] = __shfl_sync(0xffffffffu, word, half * 16 + j);

        if (active) {
            uint32_t m = word;
            while (m) {
                int b = __ffs(m) - 1;
                m &= m - 1;
                int e = (l16 & 7) * 32 + b;
                #pragma unroll
                for (int j = 0; j < 8; j++) {
                    uint32_t cur = sEdge[e * 8 + j];
                    if ((cur & wd[j]) != wd[j]) atomicOr(&sEdge[e * 8 + j], wd[j]);
                }
            }
        }
    }
    __syncthreads();
    for (int i = tid; i < N_EDGES * 8; i += 512) {
        uint32_t v = sEdge[i];
        if (v) atomicOr(&g_edgeMask[i], v);
    }
    __threadfence();
    __syncthreads();
    if (tid == 0) atomicAdd(&g_done, 1);

    // ---- rendezvous 1: all sample contributions visible ----
    spin_until(PACK1_BLOCKS);

    int bad = 0;
    for (int i = tid; i < N_EDGES * 8; i += 512)
        bad += (g_edgeMask[i] != 0xffffffffu);
    if (tid == 0) nf = 0;
    __syncthreads();
    if (bad) atomicAdd(&nf, bad);
    __syncthreads();
    const bool sat = (nf == 0);
    if (blockIdx.x == 0 && tid == 0) g_sat = sat ? 1 : 0;
    if (sat) return;

    // ======== fallback (statistically never taken; exactness guard) ========
    // ---- Phase B: pack remaining nodes (simple strided layout) ----
    const int w = tid & 7;
    for (int base = SAT_NODES + blockIdx.x * 64; base < N_NODES;
         base += PACK1_BLOCKS * 64) {
        const int node = base + (tid >> 3);
        const float4* hp = reinterpret_cast<const float4*>(
            H + (size_t)node * N_EDGES + w * 32);
        uint32_t word = 0;
        #pragma unroll
        for (int j = 0; j < 8; j++) {
            float4 f = hp[j];
            word |= (f.x >= 0.5f ? 1u : 0u) << (j * 4 + 0);
            word |= (f.y >= 0.5f ? 1u : 0u) << (j * 4 + 1);
            word |= (f.z >= 0.5f ? 1u : 0u) << (j * 4 + 2);
            word |= (f.w >= 0.5f ? 1u : 0u) << (j * 4 + 3);
        }
        g_nodeMask[node * 8 + w] = word;
        uint32_t wd[8];
        #pragma unroll
        for (int j = 0; j < 8; j++)
            wd[j] = __shfl_sync(0xffffffffu, word, (lane & ~7) | j);
        uint32_t m = word;
        while (m) {
            int b = __ffs(m) - 1;
            m &= m - 1;
            int e = w * 32 + b;
            #pragma unroll
            for (int j = 0; j < 8; j++) {
                uint32_t cur = sEdge[e * 8 + j];
                if ((cur & wd[j]) != wd[j]) atomicOr(&sEdge[e * 8 + j], wd[j]);
            }
        }
    }
    __syncthreads();
    for (int i = tid; i < N_EDGES * 8; i += 512) {
        uint32_t v = sEdge[i];
        if (v) atomicOr(&g_edgeMask[i], v);
    }
    __threadfence();
    __syncthreads();
    if (tid == 0) atomicAdd(&g_done, 1);

    // ---- rendezvous 2: full edge masks visible ----
    spin_until(2 * PACK1_BLOCKS);

    // ---- exact scale for all nodes (reuse sEdge as the mask table) ----
    for (int i = tid; i < N_EDGES * 8; i += 512) sEdge[i] = g_edgeMask[i];
    __syncthreads();

    for (int node = blockIdx.x * 512 + tid; node < N_NODES;
         node += PACK1_BLOCKS * 512) {
        const uint4 a = reinterpret_cast<const uint4*>(g_nodeMask)[node * 2 + 0];
        const uint4 b = reinterpret_cast<const uint4*>(g_nodeMask)[node * 2 + 1];
        uint32_t wd[8] = {a.x, a.y, a.z, a.w, b.x, b.y, b.z, b.w};
        int deg = 0;
        #pragma unroll
        for (int j = 0; j < 8; j++) deg += __popc(wd[j]);
        uint32_t acc[8] = {0, 0, 0, 0, 0, 0, 0, 0};
        if (deg) {
            bool fl = false;
            for (int w0 = 0; w0 < 8 && !fl; w0++) {
                uint32_t m = wd[w0];
                while (m) {
                    int bi = __ffs(m) - 1;
                    m &= m - 1;
                    int e = w0 * 32 + bi;
                    uint32_t allones = 0xffffffffu;
                    #pragma unroll
                    for (int j = 0; j < 8; j++) {
                        acc[j] |= sEdge[e * 8 + j];
                        allones &= acc[j];
                    }
                    if (allones == 0xffffffffu) { fl = true; break; }
                }
            }
        }
        int dv2 = 0;
        #pragma unroll
        for (int j = 0; j < 8; j++) dv2 += __popc(acc[j]);
        const int dv = deg + dv2;
        float s = 1.0f;
        if (dv > 0) s += rsqrtf((float)dv);
        g_scale[node] = s;
    }
}

// ---------------- K5: GEMM out = scale * (U @ W) + bias, fp16, inline H scales ----------------
#define SM_BIAS  0                       // 256 floats = 1 KB
#define SM_SCALE 1024                    // 128 floats
#define SM_AH    2048                    // 128 x 256B fp16        32 KB
#define SM_BH    (SM_AH + 32768)         // 256 x 256B fp16        64 KB
#define SM_TOTAL (SM_BH + 65536)         // 100352 bytes

__device__ __forceinline__ uint32_t sw_off(int row, int k) {     // fp16, 256B rows
    return (uint32_t)(row * 256 + ((((k >> 3) ^ (row & 7)) << 4) | ((k & 7) * 2)));
}

__device__ __forceinline__ uint32_t smem_u32(const void* p) {
    uint32_t a;
    asm("{ .reg .u64 t; cvta.to.shared.u64 t, %1; cvt.u32.u64 %0, t; }"
        : "=r"(a) : "l"(p));
    return a;
}

__device__ __forceinline__ void ldsm_x4(uint32_t* r, uint32_t addr) {
    asm volatile("ldmatrix.sync.aligned.m8n8.x4.shared.b16 {%0,%1,%2,%3}, [%4];"
                 : "=r"(r[0]), "=r"(r[1]), "=r"(r[2]), "=r"(r[3]) : "r"(addr));
}

__device__ __forceinline__ void mma16816h(float* c, const uint32_t* a, const uint32_t* b) {
    asm volatile(
        "mma.sync.aligned.m16n8k16.row.col.f32.f16.f16.f32 "
        "{%0,%1,%2,%3}, {%4,%5,%6,%7}, {%8,%9}, {%0,%1,%2,%3};"
        : "+f"(c[0]), "+f"(c[1]), "+f"(c[2]), "+f"(c[3])
        : "r"(a[0]), "r"(a[1]), "r"(a[2]), "r"(a[3]), "r"(b[0]), "r"(b[1]));
}

__device__ __forceinline__ void convertH8(const float* v, char* smem, int row, int k0,
                                          uint32_t baseH) {
    uint32_t hi[4];
    #pragma unroll
    for (int i = 0; i < 4; i++) {
        __half2 hp = __floats2half2_rn(v[2 * i + 0], v[2 * i + 1]);
        hi[i] = *reinterpret_cast<uint32_t*>(&hp);
    }
    *reinterpret_cast<uint4*>(smem + baseH + sw_off(row, k0)) =
        make_uint4(hi[0], hi[1], hi[2], hi[3]);
}

// group-scoped prefetch: 256 threads cover 64 rows x 128 cols
__device__ __forceinline__ void prefetchA_g(const float* __restrict__ U, int R0,
                                            int gid, int gtid, float4* pf) {
    #pragma unroll
    for (int it = 0; it < 4; it++) {
        const int c  = it * 256 + gtid;
        const int m  = gid * 64 + (c >> 4);
        const int k0 = (c & 15) * 8;
        const float4* up = reinterpret_cast<const float4*>(
            U + (size_t)(R0 + m) * IN_C + k0);
        pf[2 * it + 0] = up[0];
        pf[2 * it + 1] = up[1];
    }
}

__device__ __forceinline__ int cnt16(const float4* hv) {
    int c = 0;
    #pragma unroll
    for (int i = 0; i < 8; i++) {
        c += (hv[i].x >= 0.5f) + (hv[i].y >= 0.5f)
           + (hv[i].z >= 0.5f) + (hv[i].w >= 0.5f);
    }
    return c;
}

__global__ void __launch_bounds__(512, 1)
k_gemm(const float* __restrict__ H, const float* __restrict__ U,
       const float* __restrict__ W, const float* __restrict__ bias,
       float* __restrict__ out)
{
    extern __shared__ char smem[];
    const uint32_t sb = smem_u32(smem);
    const int tid  = threadIdx.x;
    const int lane = tid & 31;
    const int gid  = tid >> 8;          // warp-group 0 / 1
    const int gtid = tid & 255;
    const int gwid = gtid >> 5;         // 0..7 within group
    const int wm   = gwid >> 2;         // 0..1 (32 rows each within group's 64)
    const int wn   = gwid & 3;          // 0..3 (32 cols per half)

    float* sbias  = reinterpret_cast<float*>(smem + SM_BIAS);
    float* sscale = reinterpret_cast<float*>(smem + SM_SCALE);
    if (tid < OUT_C) sbias[tid] = bias[tid];
    const bool sat = (g_sat != 0);

    // ---- convert W once (all 512 threads): B[n][k] = W[k][n] -> fp16 ----
    #pragma unroll 1
    for (int it = 0; it < 8; it++) {
        const int idx = it * 512 + tid;
        const int n   = idx & 255;
        const int k0  = (idx >> 8) * 8;
        float v[8];
        #pragma unroll
        for (int i = 0; i < 8; i++) v[i] = W[(size_t)(k0 + i) * OUT_C + n];
        convertH8(v, smem, n, k0, SM_BH);
    }
    __syncthreads();    // B tile final; groups independent from here on

    const uint32_t xr = lane & 7;
    const int rowBase = gid * 64 + wm * 32;
    const uint32_t aRowB = (uint32_t)((rowBase + (lane & 15)) * 256);
    const int nInPair = (lane & 7) + ((lane >> 4) << 3);
    const uint32_t bKcOff = (lane >> 3) & 1;
    const uint32_t aKcOff = lane >> 4;

    // inline-H mapping: warp covers 4 rows/pass; lanes grouped 8 per row
    const int l8    = lane & 7;
    const int hRowL = gid * 64 + gwid * 4 + (lane >> 3);   // local tile row, pass adds 32

    float4 pf[8];                      // prefetched group A half-tile
    prefetchA_g(U, blockIdx.x * M_TILE, gid, gtid, pf);

    for (int tile = blockIdx.x; tile < N_TILES; tile += gridDim.x) {
        const int R0 = tile * M_TILE;

        if (sat) {
            // pass 1: H rows [hRowL, +32)
            float4 hv[8];
            {
                const float4* hp = reinterpret_cast<const float4*>(
                    H + (size_t)(R0 + hRowL) * N_EDGES) + l8;
                #pragma unroll
                for (int j = 0; j < 8; j++) hv[j] = hp[j * 8];
            }
            #pragma unroll
            for (int it = 0; it < 2; it++) {
                const int c  = it * 256 + gtid;
                const int m  = gid * 64 + (c >> 4);
                const int k0 = (c & 15) * 8;
                const float4 f0 = pf[2 * it + 0];
                const float4 f1 = pf[2 * it + 1];
                float v[8] = {f0.x, f0.y, f0.z, f0.w, f1.x, f1.y, f1.z, f1.w};
                convertH8(v, smem, m, k0, SM_AH);
            }
            {
                int c = cnt16(hv);
                c += __shfl_xor_sync(0xffffffffu, c, 1);
                c += __shfl_xor_sync(0xffffffffu, c, 2);
                c += __shfl_xor_sync(0xffffffffu, c, 4);
                if (l8 == 0)
                    sscale[hRowL] = (c > 0) ? (1.0f + rsqrtf((float)(c + 256))) : 1.0f;
            }
            // pass 2: H rows [hRowL+32, +32)
            {
                const float4* hp = reinterpret_cast<const float4*>(
                    H + (size_t)(R0 + hRowL + 32) * N_EDGES) + l8;
                #pragma unroll
                for (int j = 0; j < 8; j++) hv[j] = hp[j * 8];
            }
            #pragma unroll
            for (int it = 2; it < 4; it++) {
                const int c  = it * 256 + gtid;
                const int m  = gid * 64 + (c >> 4);
                const int k0 = (c & 15) * 8;
                const float4 f0 = pf[2 * it + 0];
                const float4 f1 = pf[2 * it + 1];
                float v[8] = {f0.x, f0.y, f0.z, f0.w, f1.x, f1.y, f1.z, f1.w};
                convertH8(v, smem, m, k0, SM_AH);
            }
            {
                int c = cnt16(hv);
                c += __shfl_xor_sync(0xffffffffu, c, 1);
                c += __shfl_xor_sync(0xffffffffu, c, 2);
                c += __shfl_xor_sync(0xffffffffu, c, 4);
                if (l8 == 0)
                    sscale[hRowL + 32] = (c > 0) ? (1.0f + rsqrtf((float)(c + 256))) : 1.0f;
            }
        } else {
            if (gtid < 64) sscale[gid * 64 + gtid] = g_scale[R0 + gid * 64 + gtid];
            #pragma unroll
            for (int it = 0; it < 4; it++) {
                const int c  = it * 256 + gtid;
                const int m  = gid * 64 + (c >> 4);
                const int k0 = (c & 15) * 8;
                const float4 f0 = pf[2 * it + 0];
                const float4 f1 = pf[2 * it + 1];
                float v[8] = {f0.x, f0.y, f0.z, f0.w, f1.x, f1.y, f1.z, f1.w};
                convertH8(v, smem, m, k0, SM_AH);
            }
        }
        asm volatile("bar.sync %0, %1;" :: "r"(gid + 1), "r"(256) : "memory");

        const int nxt = tile + gridDim.x;
        if (nxt < N_TILES) prefetchA_g(U, nxt * M_TILE, gid, gtid, pf);

        #pragma unroll 1
        for (int h = 0; h < 2; h++) {
            const int ncolw = h * 128 + wn * 32;
            float acc[32];
            #pragma unroll
            for (int i = 0; i < 32; i++) acc[i] = 0.0f;

            // ---- single fp16 pass: A x B ----
            #pragma unroll
            for (int ks = 0; ks < 8; ks++) {
                uint32_t a[2][4];
                #pragma unroll
                for (int mt = 0; mt < 2; mt++) {
                    const uint32_t kx = (((uint32_t)(2 * ks) + aKcOff) ^ xr) << 4;
                    ldsm_x4(a[mt], sb + SM_AH + aRowB + (uint32_t)(mt * 4096) + kx);
                }
                uint32_t b[2][4];
                #pragma unroll
                for (int np = 0; np < 2; np++) {
                    const int n_l = ncolw + np * 16 + nInPair;
                    const uint32_t kx = (((uint32_t)(2 * ks) + bKcOff) ^ (uint32_t)(n_l & 7)) << 4;
                    ldsm_x4(b[np], sb + SM_BH + (uint32_t)(n_l * 256) + kx);
                }
                #pragma unroll
                for (int mt = 0; mt < 2; mt++)
                    #pragma unroll
                    for (int np = 0; np < 2; np++) {
                        mma16816h(&acc[(mt * 4 + np * 2 + 0) * 4], a[mt], &b[np][0]);
                        mma16816h(&acc[(mt * 4 + np * 2 + 1) * 4], a[mt], &b[np][2]);
                    }
            }

            // ---- epilogue: out = scale[row] * acc + bias[col] ----
            #pragma unroll
            for (int mt = 0; mt < 2; mt++) {
                const int r0 = rowBase + mt * 16 + (lane >> 2);
                const float s0 = sscale[r0];
                const float s1 = sscale[r0 + 8];
                #pragma unroll
                for (int nt = 0; nt < 4; nt++) {
                    const int col = ncolw + nt * 8 + (lane & 3) * 2;
                    const float bx = sbias[col];
                    const float by = sbias[col + 1];
                    const float* c = &acc[(mt * 4 + nt) * 4];
                    float2 o0 = make_float2(c[0] * s0 + bx, c[1] * s0 + by);
                    float2 o1 = make_float2(c[2] * s1 + bx, c[3] * s1 + by);
                    *reinterpret_cast<float2*>(out + (size_t)(R0 + r0) * OUT_C + col)     = o0;
                    *reinterpret_cast<float2*>(out + (size_t)(R0 + r0 + 8) * OUT_C + col) = o1;
                }
            }
        }
        // protect this group's A smem + sscale before next tile's writes
        asm volatile("bar.sync %0, %1;" :: "r"(gid + 1), "r"(256) : "memory");
    }

    // ---- tail: reset prepass state for the next graph replay ----
    {
        const int gidx = blockIdx.x * 512 + tid;
        if (gidx < N_EDGES * 8) g_edgeMask[gidx] = 0u;
        if (gidx == 0) g_done = 0;
    }
}

// ---------------- launch (2 kernels total) ----------------
extern "C" void kernel_launch(void* const* d_in, const int* in_sizes, int n_in,
                              void* d_out, int out_size) {
    (void)in_sizes; (void)n_in; (void)out_size;
    const float* H    = (const float*)d_in[0];
    const float* U    = (const float*)d_in[1];
    const float* W    = (const float*)d_in[2];
    const float* bias = (const float*)d_in[3];
    float* out = (float*)d_out;

    k_pack1<<<PACK1_BLOCKS, 512>>>(H);   // prepass incl. saturation check + fallback

    cudaFuncSetAttribute(k_gemm, cudaFuncAttributeMaxDynamicSharedMemorySize, SM_TOTAL);
    k_gemm<<<148, 512, SM_TOTAL>>>(H, U, W, bias, out);
}

// round 17
// speedup vs baseline: 1.9883x; 1.0843x over previous
#include <cuda_runtime.h>
#include <cuda_fp16.h>
#include <stdint.h>

#define N_NODES 131072
#define N_EDGES 256
#define IN_C    128
#define OUT_C   256
#define M_TILE  128
#define N_TILES (N_NODES / M_TILE)   // 1024
#define SAT_NODES 8192
#define PACK1_BLOCKS (SAT_NODES / 64)  // 128

// ---------------- device scratch (no allocations allowed) ----------------
__device__ __align__(16) uint32_t g_nodeMask[N_NODES * 8];   // fallback only
__device__ uint32_t g_edgeMask[N_EDGES * 8];   // zero-init; reset by k_gemm tail
__device__ float    g_scale[N_NODES];          // fallback only
__device__ int      g_sat;
__device__ int      g_done;                    // zero-init; reset by k_gemm tail

__device__ __forceinline__ void spin_until(int target) {
    if (threadIdx.x == 0) {
        while (atomicAdd(&g_done, 0) < target) { }
    }
    __syncthreads();
    __threadfence();
}

// ---------------- K1: full prepass in one launch (unchanged from R16) ----------------
__global__ void __launch_bounds__(512) k_pack1(const float* __restrict__ H) {
    __shared__ uint32_t sEdge[N_EDGES * 8];
    __shared__ int nf;
    const int tid  = threadIdx.x;
    const int lane = tid & 31;
    const int wId  = tid >> 5;
    const int l16  = lane & 15;
    const int half = lane >> 4;

    for (int i = tid; i < N_EDGES * 8; i += 512) sEdge[i] = 0u;
    __syncthreads();

    #pragma unroll
    for (int s = 0; s < 2; s++) {
        const int node = blockIdx.x * 64 + s * 32 + wId * 2 + half;
        const float4* hp = reinterpret_cast<const float4*>(
            H + (size_t)node * N_EDGES) + l16;
        uint32_t pack = 0;
        #pragma unroll
        for (int j = 0; j < 4; j++) {
            const float4 f = hp[j * 16];
            uint32_t nib = (f.x >= 0.5f ? 1u : 0u)
                         | (f.y >= 0.5f ? 2u : 0u)
                         | (f.z >= 0.5f ? 4u : 0u)
                         | (f.w >= 0.5f ? 8u : 0u);
            pack |= nib << (4 * j);
        }
        uint32_t word = 0;
        {
            const int w = l16 & 7;
            const int j = w >> 1;
            const int srcBase = half * 16 + (w & 1) * 8;
            #pragma unroll
            for (int i = 0; i < 8; i++) {
                uint32_t p = __shfl_sync(0xffffffffu, pack, srcBase + i);
                word |= ((p >> (4 * j)) & 0xFu) << (4 * i);
            }
        }
        const bool active = (l16 < 8);
        if (active) g_nodeMask[node * 8 + l16] = word;

        uint32_t wd[8];
        #pragma unroll
        for (int j = 0; j < 8; j++)
            wd[j] = __shfl_sync(0xffffffffu, word, half * 16 + j);

        if (active) {
            uint32_t m = word;
            while (m) {
                int b = __ffs(m) - 1;
                m &= m - 1;
                int e = (l16 & 7) * 32 + b;
                #pragma unroll
                for (int j = 0; j < 8; j++) {
                    uint32_t cur = sEdge[e * 8 + j];
                    if ((cur & wd[j]) != wd[j]) atomicOr(&sEdge[e * 8 + j], wd[j]);
                }
            }
        }
    }
    __syncthreads();
    for (int i = tid; i < N_EDGES * 8; i += 512) {
        uint32_t v = sEdge[i];
        if (v) atomicOr(&g_edgeMask[i], v);
    }
    __threadfence();
    __syncthreads();
    if (tid == 0) atomicAdd(&g_done, 1);

    spin_until(PACK1_BLOCKS);

    int bad = 0;
    for (int i = tid; i < N_EDGES * 8; i += 512)
        bad += (g_edgeMask[i] != 0xffffffffu);
    if (tid == 0) nf = 0;
    __syncthreads();
    if (bad) atomicAdd(&nf, bad);
    __syncthreads();
    const bool sat = (nf == 0);
    if (blockIdx.x == 0 && tid == 0) g_sat = sat ? 1 : 0;
    if (sat) return;

    // ======== fallback (statistically never taken) ========
    const int w = tid & 7;
    for (int base = SAT_NODES + blockIdx.x * 64; base < N_NODES;
         base += PACK1_BLOCKS * 64) {
        const int node = base + (tid >> 3);
        const float4* hp = reinterpret_cast<const float4*>(
            H + (size_t)node * N_EDGES + w * 32);
        uint32_t word = 0;
        #pragma unroll
        for (int j = 0; j < 8; j++) {
            float4 f = hp[j];
            word |= (f.x >= 0.5f ? 1u : 0u) << (j * 4 + 0);
            word |= (f.y >= 0.5f ? 1u : 0u) << (j * 4 + 1);
            word |= (f.z >= 0.5f ? 1u : 0u) << (j * 4 + 2);
            word |= (f.w >= 0.5f ? 1u : 0u) << (j * 4 + 3);
        }
        g_nodeMask[node * 8 + w] = word;
        uint32_t wd[8];
        #pragma unroll
        for (int j = 0; j < 8; j++)
            wd[j] = __shfl_sync(0xffffffffu, word, (lane & ~7) | j);
        uint32_t m = word;
        while (m) {
            int b = __ffs(m) - 1;
            m &= m - 1;
            int e = w * 32 + b;
            #pragma unroll
            for (int j = 0; j < 8; j++) {
                uint32_t cur = sEdge[e * 8 + j];
                if ((cur & wd[j]) != wd[j]) atomicOr(&sEdge[e * 8 + j], wd[j]);
            }
        }
    }
    __syncthreads();
    for (int i = tid; i < N_EDGES * 8; i += 512) {
        uint32_t v = sEdge[i];
        if (v) atomicOr(&g_edgeMask[i], v);
    }
    __threadfence();
    __syncthreads();
    if (tid == 0) atomicAdd(&g_done, 1);

    spin_until(2 * PACK1_BLOCKS);

    for (int i = tid; i < N_EDGES * 8; i += 512) sEdge[i] = g_edgeMask[i];
    __syncthreads();

    for (int node = blockIdx.x * 512 + tid; node < N_NODES;
         node += PACK1_BLOCKS * 512) {
        const uint4 a = reinterpret_cast<const uint4*>(g_nodeMask)[node * 2 + 0];
        const uint4 b = reinterpret_cast<const uint4*>(g_nodeMask)[node * 2 + 1];
        uint32_t wd[8] = {a.x, a.y, a.z, a.w, b.x, b.y, b.z, b.w};
        int deg = 0;
        #pragma unroll
        for (int j = 0; j < 8; j++) deg += __popc(wd[j]);
        uint32_t acc[8] = {0, 0, 0, 0, 0, 0, 0, 0};
        if (deg) {
            bool fl = false;
            for (int w0 = 0; w0 < 8 && !fl; w0++) {
                uint32_t m = wd[w0];
                while (m) {
                    int bi = __ffs(m) - 1;
                    m &= m - 1;
                    int e = w0 * 32 + bi;
                    uint32_t allones = 0xffffffffu;
                    #pragma unroll
                    for (int j = 0; j < 8; j++) {
                        acc[j] |= sEdge[e * 8 + j];
                        allones &= acc[j];
                    }
                    if (allones == 0xffffffffu) { fl = true; break; }
                }
            }
        }
        int dv2 = 0;
        #pragma unroll
        for (int j = 0; j < 8; j++) dv2 += __popc(acc[j]);
        const int dv = deg + dv2;
        float s = 1.0f;
        if (dv > 0) s += rsqrtf((float)dv);
        g_scale[node] = s;
    }
}

// ---------------- K5: GEMM, fp16, fully pipelined load streams ----------------
// U via cp.async -> fp32 staging (per-thread slices, no cross-thread sync).
// H for tile t+1 prefetched into registers across the MMA halves.
// sscale double-buffered.
#define SM_BIAS  0                       // 256 floats = 1 KB
#define SM_SCALE 1024                    // 2 x 128 floats = 1 KB
#define SM_AH    2048                    // 128 x 256B fp16        32 KB
#define SM_BH    (SM_AH + 32768)         // 256 x 256B fp16        64 KB
#define SM_UST   (SM_BH + 65536)         // 2 groups x 32KB fp32   64 KB
#define SM_TOTAL (SM_UST + 65536)        // 165888 bytes

#define CP_ASYNC16(sm, gm) \
    asm volatile("cp.async.cg.shared.global [%0], [%1], 16;" \
                 :: "r"(sm), "l"(gm) : "memory")

__device__ __forceinline__ uint32_t sw_off(int row, int k) {     // fp16, 256B rows
    return (uint32_t)(row * 256 + ((((k >> 3) ^ (row & 7)) << 4) | ((k & 7) * 2)));
}

__device__ __forceinline__ uint32_t smem_u32(const void* p) {
    uint32_t a;
    asm("{ .reg .u64 t; cvta.to.shared.u64 t, %1; cvt.u32.u64 %0, t; }"
        : "=r"(a) : "l"(p));
    return a;
}

__device__ __forceinline__ void ldsm_x4(uint32_t* r, uint32_t addr) {
    asm volatile("ldmatrix.sync.aligned.m8n8.x4.shared.b16 {%0,%1,%2,%3}, [%4];"
                 : "=r"(r[0]), "=r"(r[1]), "=r"(r[2]), "=r"(r[3]) : "r"(addr));
}

__device__ __forceinline__ void mma16816h(float* c, const uint32_t* a, const uint32_t* b) {
    asm volatile(
        "mma.sync.aligned.m16n8k16.row.col.f32.f16.f16.f32 "
        "{%0,%1,%2,%3}, {%4,%5,%6,%7}, {%8,%9}, {%0,%1,%2,%3};"
        : "+f"(c[0]), "+f"(c[1]), "+f"(c[2]), "+f"(c[3])
        : "r"(a[0]), "r"(a[1]), "r"(a[2]), "r"(a[3]), "r"(b[0]), "r"(b[1]));
}

__device__ __forceinline__ void convertH8(const float* v, char* smem, int row, int k0,
                                          uint32_t baseH) {
    uint32_t hi[4];
    #pragma unroll
    for (int i = 0; i < 4; i++) {
        __half2 hp = __floats2half2_rn(v[2 * i + 0], v[2 * i + 1]);
        hi[i] = *reinterpret_cast<uint32_t*>(&hp);
    }
    *reinterpret_cast<uint4*>(smem + baseH + sw_off(row, k0)) =
        make_uint4(hi[0], hi[1], hi[2], hi[3]);
}

__device__ __forceinline__ int cnt16(const float4* hv) {
    int c = 0;
    #pragma unroll
    for (int i = 0; i < 8; i++) {
        c += (hv[i].x >= 0.5f) + (hv[i].y >= 0.5f)
           + (hv[i].z >= 0.5f) + (hv[i].w >= 0.5f);
    }
    return c;
}

// issue cp.async of this thread's U slice for a tile into the staging buffer
__device__ __forceinline__ void cpAsyncU(const float* __restrict__ U, int R0,
                                         int gid, int gtid, uint32_t sb) {
    #pragma unroll
    for (int it = 0; it < 4; it++) {
        const int c  = it * 256 + gtid;
        const int lm = c >> 4;              // 0..63 (group-local row)
        const int k0 = (c & 15) * 8;
        const float* src = U + (size_t)(R0 + gid * 64 + lm) * IN_C + k0;
        const uint32_t dst = sb + SM_UST + (uint32_t)(gid * 32768 + lm * 512 + k0 * 4);
        CP_ASYNC16(dst, src);
        CP_ASYNC16(dst + 16, src + 4);
    }
    asm volatile("cp.async.commit_group;" ::: "memory");
}

__global__ void __launch_bounds__(512, 1)
k_gemm(const float* __restrict__ H, const float* __restrict__ U,
       const float* __restrict__ W, const float* __restrict__ bias,
       float* __restrict__ out)
{
    extern __shared__ char smem[];
    const uint32_t sb = smem_u32(smem);
    const int tid  = threadIdx.x;
    const int lane = tid & 31;
    const int gid  = tid >> 8;          // warp-group 0 / 1
    const int gtid = tid & 255;
    const int gwid = gtid >> 5;         // 0..7 within group
    const int wm   = gwid >> 2;         // 0..1
    const int wn   = gwid & 3;          // 0..3

    float* sbias  = reinterpret_cast<float*>(smem + SM_BIAS);
    float* sscale = reinterpret_cast<float*>(smem + SM_SCALE);  // 2 x 128
    if (tid < OUT_C) sbias[tid] = bias[tid];
    const bool sat = (g_sat != 0);

    // ---- convert W once: B[n][k] = W[k][n] -> fp16 ----
    #pragma unroll 1
    for (int it = 0; it < 8; it++) {
        const int idx = it * 512 + tid;
        const int n   = idx & 255;
        const int k0  = (idx >> 8) * 8;
        float v[8];
        #pragma unroll
        for (int i = 0; i < 8; i++) v[i] = W[(size_t)(k0 + i) * OUT_C + n];
        convertH8(v, smem, n, k0, SM_BH);
    }
    __syncthreads();

    const uint32_t xr = lane & 7;
    const int rowBase = gid * 64 + wm * 32;
    const uint32_t aRowB = (uint32_t)((rowBase + (lane & 15)) * 256);
    const int nInPair = (lane & 7) + ((lane >> 4) << 3);
    const uint32_t bKcOff = (lane >> 3) & 1;
    const uint32_t aKcOff = lane >> 4;

    // inline-H mapping: warp covers 4 rows/pass, 8 lanes per row
    const int l8    = lane & 7;
    const int hRowL = gid * 64 + gwid * 4 + (lane >> 3);

    // ---- prologue: stage U(t0), compute scales(t0) into sscale buf 0 ----
    int p = 0;
    {
        const int t0 = blockIdx.x;
        cpAsyncU(U, t0 * M_TILE, gid, gtid, sb);
        if (sat) {
            float4 hv[8];
            const float4* hp = reinterpret_cast<const float4*>(
                H + (size_t)(t0 * M_TILE + hRowL) * N_EDGES) + l8;
            #pragma unroll
            for (int j = 0; j < 8; j++) hv[j] = hp[j * 8];
            int c = cnt16(hv);
            c += __shfl_xor_sync(0xffffffffu, c, 1);
            c += __shfl_xor_sync(0xffffffffu, c, 2);
            c += __shfl_xor_sync(0xffffffffu, c, 4);
            if (l8 == 0)
                sscale[hRowL] = (c > 0) ? (1.0f + rsqrtf((float)(c + 256))) : 1.0f;
            hp = reinterpret_cast<const float4*>(
                H + (size_t)(t0 * M_TILE + hRowL + 32) * N_EDGES) + l8;
            #pragma unroll
            for (int j = 0; j < 8; j++) hv[j] = hp[j * 8];
            c = cnt16(hv);
            c += __shfl_xor_sync(0xffffffffu, c, 1);
            c += __shfl_xor_sync(0xffffffffu, c, 2);
            c += __shfl_xor_sync(0xffffffffu, c, 4);
            if (l8 == 0)
                sscale[hRowL + 32] = (c > 0) ? (1.0f + rsqrtf((float)(c + 256))) : 1.0f;
        } else if (gtid < 64) {
            sscale[gid * 64 + gtid] = g_scale[t0 * M_TILE + gid * 64 + gtid];
        }
    }

    for (int tile = blockIdx.x; tile < N_TILES; tile += gridDim.x, p ^= 1) {
        const int R0  = tile * M_TILE;
        const int nxt = tile + gridDim.x;
        const bool hasNext = (nxt < N_TILES);

        // ---- convert A(t) from this thread's staged U slice ----
        asm volatile("cp.async.wait_group 0;" ::: "memory");
        #pragma unroll
        for (int it = 0; it < 4; it++) {
            const int c  = it * 256 + gtid;
            const int lm = c >> 4;
            const int k0 = (c & 15) * 8;
            const float4* sp = reinterpret_cast<const float4*>(
                smem + SM_UST + gid * 32768 + lm * 512 + k0 * 4);
            const float4 f0 = sp[0];
            const float4 f1 = sp[1];
            float v[8] = {f0.x, f0.y, f0.z, f0.w, f1.x, f1.y, f1.z, f1.w};
            convertH8(v, smem, gid * 64 + lm, k0, SM_AH);
        }
        asm volatile("bar.sync %0, %1;" :: "r"(gid + 1), "r"(256) : "memory");

        // ---- issue next tile's load streams (land under the MMAs below) ----
        if (hasNext) cpAsyncU(U, nxt * M_TILE, gid, gtid, sb);
        float4 hv[8];
        float gsc = 0.0f;
        if (hasNext) {
            if (sat) {
                const float4* hp = reinterpret_cast<const float4*>(
                    H + (size_t)(nxt * M_TILE + hRowL) * N_EDGES) + l8;
                #pragma unroll
                for (int j = 0; j < 8; j++) hv[j] = hp[j * 8];
            } else if (gtid < 64) {
                gsc = g_scale[nxt * M_TILE + gid * 64 + gtid];
            }
        }

        #pragma unroll 1
        for (int h = 0; h < 2; h++) {
            const int ncolw = h * 128 + wn * 32;
            float acc[32];
            #pragma unroll
            for (int i = 0; i < 32; i++) acc[i] = 0.0f;

            #pragma unroll
            for (int ks = 0; ks < 8; ks++) {
                uint32_t a[2][4];
                #pragma unroll
                for (int mt = 0; mt < 2; mt++) {
                    const uint32_t kx = (((uint32_t)(2 * ks) + aKcOff) ^ xr) << 4;
                    ldsm_x4(a[mt], sb + SM_AH + aRowB + (uint32_t)(mt * 4096) + kx);
                }
                uint32_t b[2][4];
                #pragma unroll
                for (int np = 0; np < 2; np++) {
                    const int n_l = ncolw + np * 16 + nInPair;
                    const uint32_t kx = (((uint32_t)(2 * ks) + bKcOff) ^ (uint32_t)(n_l & 7)) << 4;
                    ldsm_x4(b[np], sb + SM_BH + (uint32_t)(n_l * 256) + kx);
                }
                #pragma unroll
                for (int mt = 0; mt < 2; mt++)
                    #pragma unroll
                    for (int np = 0; np < 2; np++) {
                        mma16816h(&acc[(mt * 4 + np * 2 + 0) * 4], a[mt], &b[np][0]);
                        mma16816h(&acc[(mt * 4 + np * 2 + 1) * 4], a[mt], &b[np][2]);
                    }
            }

            // ---- epilogue: out = scale[row] * acc + bias[col] ----
            #pragma unroll
            for (int mt = 0; mt < 2; mt++) {
                const int r0 = rowBase + mt * 16 + (lane >> 2);
                const float s0 = sscale[p * 128 + r0];
                const float s1 = sscale[p * 128 + r0 + 8];
                #pragma unroll
                for (int nt = 0; nt < 4; nt++) {
                    const int col = ncolw + nt * 8 + (lane & 3) * 2;
                    const float bx = sbias[col];
                    const float by = sbias[col + 1];
                    const float* c = &acc[(mt * 4 + nt) * 4];
                    float2 o0 = make_float2(c[0] * s0 + bx, c[1] * s0 + by);
                    float2 o1 = make_float2(c[2] * s1 + bx, c[3] * s1 + by);
                    *reinterpret_cast<float2*>(out + (size_t)(R0 + r0) * OUT_C + col)     = o0;
                    *reinterpret_cast<float2*>(out + (size_t)(R0 + r0 + 8) * OUT_C + col) = o1;
                }
            }

            // between the halves: retire H pass A, launch pass B
            if (h == 0 && hasNext && sat) {
                int c = cnt16(hv);
                c += __shfl_xor_sync(0xffffffffu, c, 1);
                c += __shfl_xor_sync(0xffffffffu, c, 2);
                c += __shfl_xor_sync(0xffffffffu, c, 4);
                if (l8 == 0)
                    sscale[(p ^ 1) * 128 + hRowL] =
                        (c > 0) ? (1.0f + rsqrtf((float)(c + 256))) : 1.0f;
                const float4* hp = reinterpret_cast<const float4*>(
                    H + (size_t)(nxt * M_TILE + hRowL + 32) * N_EDGES) + l8;
                #pragma unroll
                for (int j = 0; j < 8; j++) hv[j] = hp[j * 8];
            }
        }

        // retire H pass B / fallback scale into the next buffer
        if (hasNext) {
            if (sat) {
                int c = cnt16(hv);
                c += __shfl_xor_sync(0xffffffffu, c, 1);
                c += __shfl_xor_sync(0xffffffffu, c, 2);
                c += __shfl_xor_sync(0xffffffffu, c, 4);
                if (l8 == 0)
                    sscale[(p ^ 1) * 128 + hRowL + 32] =
                        (c > 0) ? (1.0f + rsqrtf((float)(c + 256))) : 1.0f;
            } else if (gtid < 64) {
                sscale[(p ^ 1) * 128 + gid * 64 + gtid] = gsc;
            }
        }
        // protect this group's A smem + sscale[p^1] before next tile
        asm volatile("bar.sync %0, %1;" :: "r"(gid + 1), "r"(256) : "memory");
    }

    // ---- tail: reset prepass state for the next graph replay ----
    {
        const int gidx = blockIdx.x * 512 + tid;
        if (gidx < N_EDGES * 8) g_edgeMask[gidx] = 0u;
        if (gidx == 0) g_done = 0;
    }
}

// ---------------- launch (2 kernels total) ----------------
extern "C" void kernel_launch(void* const* d_in, const int* in_sizes, int n_in,
                              void* d_out, int out_size) {
    (void)in_sizes; (void)n_in; (void)out_size;
    const float* H    = (const float*)d_in[0];
    const float* U    = (const float*)d_in[1];
    const float* W    = (const float*)d_in[2];
    const float* bias = (const float*)d_in[3];
    float* out = (float*)d_out;

    k_pack1<<<PACK1_BLOCKS, 512>>>(H);   // prepass incl. saturation check + fallback

    cudaFuncSetAttribute(k_gemm, cudaFuncAttributeMaxDynamicSharedMemorySize, SM_TOTAL);
    k_gemm<<<148, 512, SM_TOTAL>>>(H, U, W, bias, out);
}